// round 10
// baseline (speedup 1.0000x reference)
#include <cuda_runtime.h>
#include <cuda_fp16.h>
#include <math.h>

// ---------------- problem constants ----------------
#define BATCH 2
#define SEQ   1024
#define DIM   1024
#define HDIM  256
#define MBITS 32
#define NTOK  (BATCH*SEQ)     // 2048
#define PROJ  192             // 6 groups x 32
#define SCALEF 0.17677669529663687f  // 1/sqrt(32)

// ---------------- device scratch (static, no allocs) ----------------
__device__ float    g_qproj[NTOK*PROJ];
__device__ float    g_kproj[NTOK*PROJ];
__device__ unsigned g_qbits[NTOK*2];
__device__ unsigned g_kbits[NTOK*2];
__device__ float    g_Vp[NTOK*4*HDIM];
__device__ float    g_cat[NTOK*4*HDIM];
__device__ float    g_S[8u*1024u*1024u];   // [b*4+head][q][k] scores, 32MB
__device__ float    g_m[8*1024];           // row max
__device__ float    g_il[8*1024];          // 1/row sumexp

// ---------------- fp16 mma helpers ----------------
__device__ __forceinline__ unsigned pack_h2(float lo, float hi) {
    __half2 h = __floats2half2_rn(lo, hi);
    return *(unsigned*)&h;
}
__device__ __forceinline__ void mma_f16(float c[4],
    unsigned a0, unsigned a1, unsigned a2, unsigned a3,
    unsigned b0, unsigned b1)
{
    asm("mma.sync.aligned.m16n8k16.row.col.f32.f16.f16.f32 "
        "{%0,%1,%2,%3},{%4,%5,%6,%7},{%8,%9},{%0,%1,%2,%3};"
        : "+f"(c[0]), "+f"(c[1]), "+f"(c[2]), "+f"(c[3])
        : "r"(a0), "r"(a1), "r"(a2), "r"(a3), "r"(b0), "r"(b1));
}

// ---------------- 512-thread fp16 GEMM core: 128x128 tile, BK=32 ----------
// A[M,K] row-major fp32, W[N,K] row-major fp32 (B^T), C row-major fp32.
// smem half2 k-pairs: As[kk][m] = {A[m][2kk], A[m][2kk+1]}, kk 0..15.
__device__ __forceinline__ void tc512h_core(
    const float* __restrict__ A, const float* __restrict__ W,
    const float* __restrict__ bias, float* __restrict__ C,
    int K, int ldc, int bm, int bn)
{
    __shared__ unsigned As[2][16][136];
    __shared__ unsigned Ws[2][16][136];

    const int tid = threadIdx.x;
    const int w = tid >> 5, lane = tid & 31;
    const int wm = w >> 2, wn = w & 3;          // 4x4 warp grid, 32x32 tiles
    const int qr = lane >> 2, qc = lane & 3;

    const bool isA = tid < 256;
    const int st = isA ? tid : tid - 256;
    const int srow = st >> 1, sk16 = (st & 1) * 16, skk = (st & 1) * 8;
    const float* Sptr = isA ? A + (size_t)(bm + srow)*K + sk16
                            : W + (size_t)(bn + srow)*K + sk16;

    float acc[2][4][4];
    #pragma unroll
    for (int i = 0; i < 2; ++i)
        #pragma unroll
        for (int j = 0; j < 4; ++j)
            #pragma unroll
            for (int r = 0; r < 4; ++r) acc[i][j][r] = 0.f;

    const int nt = K >> 5;
    float4 s0 = *(const float4*)Sptr;
    float4 s1 = *(const float4*)(Sptr + 4);
    float4 s2 = *(const float4*)(Sptr + 8);
    float4 s3 = *(const float4*)(Sptr + 12);
    {
        unsigned* dst = isA ? &As[0][0][0] : &Ws[0][0][0];
        dst[(skk+0)*136+srow] = pack_h2(s0.x, s0.y);
        dst[(skk+1)*136+srow] = pack_h2(s0.z, s0.w);
        dst[(skk+2)*136+srow] = pack_h2(s1.x, s1.y);
        dst[(skk+3)*136+srow] = pack_h2(s1.z, s1.w);
        dst[(skk+4)*136+srow] = pack_h2(s2.x, s2.y);
        dst[(skk+5)*136+srow] = pack_h2(s2.z, s2.w);
        dst[(skk+6)*136+srow] = pack_h2(s3.x, s3.y);
        dst[(skk+7)*136+srow] = pack_h2(s3.z, s3.w);
    }
    __syncthreads();

    for (int t = 0; t < nt; ++t) {
        const int cur = t & 1;
        if (t + 1 < nt) {
            s0 = *(const float4*)(Sptr + (t+1)*32);
            s1 = *(const float4*)(Sptr + (t+1)*32 + 4);
            s2 = *(const float4*)(Sptr + (t+1)*32 + 8);
            s3 = *(const float4*)(Sptr + (t+1)*32 + 12);
        }
        #pragma unroll
        for (int ks = 0; ks < 2; ++ks) {
            const int kb = ks*8;
            unsigned af[2][4], bf[4][2];
            #pragma unroll
            for (int i = 0; i < 2; ++i) {
                int m0 = wm*32 + i*16 + qr;
                af[i][0] = As[cur][kb+qc  ][m0];
                af[i][1] = As[cur][kb+qc  ][m0+8];
                af[i][2] = As[cur][kb+qc+4][m0];
                af[i][3] = As[cur][kb+qc+4][m0+8];
            }
            #pragma unroll
            for (int j = 0; j < 4; ++j) {
                int n0 = wn*32 + j*8 + qr;
                bf[j][0] = Ws[cur][kb+qc  ][n0];
                bf[j][1] = Ws[cur][kb+qc+4][n0];
            }
            #pragma unroll
            for (int i = 0; i < 2; ++i)
                #pragma unroll
                for (int j = 0; j < 4; ++j)
                    mma_f16(acc[i][j], af[i][0], af[i][1], af[i][2], af[i][3],
                            bf[j][0], bf[j][1]);
        }
        if (t + 1 < nt) {
            const int nxt = cur ^ 1;
            unsigned* dst = isA ? &As[nxt][0][0] : &Ws[nxt][0][0];
            dst[(skk+0)*136+srow] = pack_h2(s0.x, s0.y);
            dst[(skk+1)*136+srow] = pack_h2(s0.z, s0.w);
            dst[(skk+2)*136+srow] = pack_h2(s1.x, s1.y);
            dst[(skk+3)*136+srow] = pack_h2(s1.z, s1.w);
            dst[(skk+4)*136+srow] = pack_h2(s2.x, s2.y);
            dst[(skk+5)*136+srow] = pack_h2(s2.z, s2.w);
            dst[(skk+6)*136+srow] = pack_h2(s3.x, s3.y);
            dst[(skk+7)*136+srow] = pack_h2(s3.z, s3.w);
        }
        __syncthreads();
    }

    #pragma unroll
    for (int i = 0; i < 2; ++i) {
        int r0 = bm + wm*32 + i*16 + qr;
        #pragma unroll
        for (int j = 0; j < 4; ++j) {
            int c0 = bn + wn*32 + j*8 + 2*qc;
            float bx = 0.f, by = 0.f;
            if (bias) { bx = bias[c0]; by = bias[c0+1]; }
            float2 o0, o1;
            o0.x = acc[i][j][0] + bx; o0.y = acc[i][j][1] + by;
            o1.x = acc[i][j][2] + bx; o1.y = acc[i][j][3] + by;
            *(float2*)&C[(size_t)r0*ldc + c0]     = o0;
            *(float2*)&C[(size_t)(r0+8)*ldc + c0] = o1;
        }
    }
}

// ---------------- fused front-end: V-proj (blocks 0..127) + QK-proj -------
// QK: 64x64 fp32 tiles, weights read directly from input pointers (no pack).
__global__ __launch_bounds__(512) void fused_qkv(
    const float* __restrict__ Vin,
    const float* __restrict__ b_v, const float* __restrict__ t_v,
    const float* __restrict__ r_v, const float* __restrict__ p_v,
    const float* __restrict__ Qin, const float* __restrict__ Kin,
    const float* __restrict__ bq_w, const float* __restrict__ tq_w,
    const float* __restrict__ rq_w, const float* __restrict__ pq_w,
    const float* __restrict__ bk_w, const float* __restrict__ tk_w,
    const float* __restrict__ rk_w, const float* __restrict__ pk_w,
    const float* __restrict__ bq_b, const float* __restrict__ tq_b,
    const float* __restrict__ rq_b, const float* __restrict__ pq_b,
    const float* __restrict__ bk_b, const float* __restrict__ tk_b,
    const float* __restrict__ rk_b, const float* __restrict__ pk_b,
    float* __restrict__ Vp)
{
    const int bid = blockIdx.x;
    if (bid < 128) {
        // ---- V projection, fp16 core, per-head weight, strided output ----
        const int head = bid >> 5, r = bid & 31;
        const int by = r >> 1, bx = r & 1;
        const float* W = (head == 0) ? b_v : (head == 1) ? t_v
                       : (head == 2) ? r_v : p_v;
        tc512h_core(Vin, W, nullptr, Vp + head*HDIM,
                    DIM, 4*HDIM, by*128, bx*128);
        return;
    }

    // ---- QK projection: exact fp32, 64x64 tile, 512 threads ----
    __shared__ __align__(16) float As[2][8][68];
    __shared__ __align__(16) float Ws[2][8][68];

    const int q = bid - 128;
    const int z = q / 96, rr = q % 96;
    const int bn = (rr % 3) * 64, bm = (rr / 3) * 64;

    const float* A = z ? Kin : Qin;
    float*       C = z ? g_kproj : g_qproj;
    const float* wsrc[6];
    const float* bsrc[6];
    if (z) {
        wsrc[0]=bk_w; wsrc[1]=tk_w; wsrc[2]=rk_w;
        wsrc[3]=pk_w; wsrc[4]=pk_w+(size_t)32*DIM; wsrc[5]=pk_w+(size_t)64*DIM;
        bsrc[0]=bk_b; bsrc[1]=tk_b; bsrc[2]=rk_b;
        bsrc[3]=pk_b; bsrc[4]=pk_b+32; bsrc[5]=pk_b+64;
    } else {
        wsrc[0]=bq_w; wsrc[1]=tq_w; wsrc[2]=rq_w;
        wsrc[3]=pq_w; wsrc[4]=pq_w+(size_t)32*DIM; wsrc[5]=pq_w+(size_t)64*DIM;
        bsrc[0]=bq_b; bsrc[1]=tq_b; bsrc[2]=rq_b;
        bsrc[3]=pq_b; bsrc[4]=pq_b+32; bsrc[5]=pq_b+64;
    }

    const int tid = threadIdx.x;
    const int tx = tid & 15, ty = tid >> 4;   // compute: 2 rows x 4 cols each
    const bool stg = tid < 256;
    const bool isA = tid < 128;
    const int st = isA ? tid : tid - 128;
    const int srow = st >> 1, sc4 = (st & 1) * 4;

    const float* Sptr = nullptr;
    if (stg) {
        if (isA) Sptr = A + (size_t)(bm + srow)*DIM + sc4;
        else {
            int wr = bn + srow;
            Sptr = wsrc[wr >> 5] + (size_t)(wr & 31)*DIM + sc4;
        }
    }

    float acc[2][4];
    #pragma unroll
    for (int i = 0; i < 2; ++i)
        #pragma unroll
        for (int j = 0; j < 4; ++j) acc[i][j] = 0.f;

    const int nt = DIM >> 3;
    float4 sreg = make_float4(0,0,0,0);
    if (stg) {
        sreg = *(const float4*)Sptr;
        #pragma unroll
        for (int j = 0; j < 4; ++j) {
            if (isA) As[0][sc4+j][srow] = (&sreg.x)[j];
            else     Ws[0][sc4+j][srow] = (&sreg.x)[j];
        }
    }
    __syncthreads();

    for (int t = 0; t < nt; ++t) {
        const int cur = t & 1;
        if (stg && t + 1 < nt) sreg = *(const float4*)(Sptr + (t+1)*8);
        #pragma unroll
        for (int kk = 0; kk < 8; ++kk) {
            float2 a2 = *(const float2*)&As[cur][kk][ty*2];
            float4 b4 = *(const float4*)&Ws[cur][kk][tx*4];
            acc[0][0] += a2.x*b4.x; acc[0][1] += a2.x*b4.y;
            acc[0][2] += a2.x*b4.z; acc[0][3] += a2.x*b4.w;
            acc[1][0] += a2.y*b4.x; acc[1][1] += a2.y*b4.y;
            acc[1][2] += a2.y*b4.z; acc[1][3] += a2.y*b4.w;
        }
        if (stg && t + 1 < nt) {
            const int nxt = cur ^ 1;
            #pragma unroll
            for (int j = 0; j < 4; ++j) {
                if (isA) As[nxt][sc4+j][srow] = (&sreg.x)[j];
                else     Ws[nxt][sc4+j][srow] = (&sreg.x)[j];
            }
        }
        __syncthreads();
    }

    const int col = bn + tx*4;
    const float* bb = bsrc[col >> 5] + ((col & 31));
    #pragma unroll
    for (int i = 0; i < 2; ++i) {
        int row = bm + ty*2 + i;
        float4 o;
        o.x = acc[i][0] + bb[0];
        o.y = acc[i][1] + bb[1];
        o.z = acc[i][2] + bb[2];
        o.w = acc[i][3] + bb[3];
        *(float4*)&C[(size_t)row*PROJ + col] = o;
    }
}

// out-proj: C[2048,1024] = cat * out_w^T + out_b
__global__ __launch_bounds__(512) void gemm_tc512(
    const float* __restrict__ A, const float* __restrict__ W,
    const float* __restrict__ bias, float* __restrict__ C,
    int K, int ldc)
{
    tc512h_core(A, W, bias, C, K, ldc, blockIdx.y*128, blockIdx.x*128);
}

// ---------------- PV GEMM, fp16 mma, BK=32, fused exp weighting -----------
__global__ __launch_bounds__(512) void gemm_pv512()
{
    __shared__ unsigned As[2][16][136];
    __shared__ unsigned Ws[2][16][136];

    const int bh = blockIdx.z, b = bh >> 2, head = bh & 3;
    const int bm = blockIdx.y * 128, bn = blockIdx.x * 128;
    const int tid = threadIdx.x;
    const int w = tid >> 5, lane = tid & 31;
    const int wm = w >> 2, wn = w & 3;
    const int qr = lane >> 2, qc = lane & 3;

    const bool isA = tid < 256;
    const int st = isA ? tid : tid - 256;
    // A: S rows, exp-weighted; thread covers 16 k (pair slots skk..skk+7)
    const int lrow = st >> 1, sk16 = (st & 1) * 16, skk = (st & 1) * 8;
    const float* Aptr = g_S + ((size_t)bh << 20) + (size_t)(bm + lrow)*1024 + sk16;
    const float mrow  = g_m [bh*1024 + bm + lrow];
    const float ilrow = g_il[bh*1024 + bm + lrow];
    // W: Vp row-pairs; thread handles pair-groups kq and kq+8, 4 cols each
    const int kq = st >> 5, n4 = st & 31;
    const float* Wptr = g_Vp + (size_t)(b*SEQ + 2*kq)*1024 + head*HDIM + bn + n4*4;

    float acc[2][4][4];
    #pragma unroll
    for (int i = 0; i < 2; ++i)
        #pragma unroll
        for (int j = 0; j < 4; ++j)
            #pragma unroll
            for (int r = 0; r < 4; ++r) acc[i][j][r] = 0.f;

    const int nt = 32;   // K=1024, BK=32
    float4 s0, s1, s2, s3;
    if (isA) {
        s0 = *(const float4*)Aptr;       s1 = *(const float4*)(Aptr + 4);
        s2 = *(const float4*)(Aptr + 8); s3 = *(const float4*)(Aptr + 12);
        float p[16];
        #pragma unroll
        for (int j = 0; j < 4; ++j) {
            p[j]    = __expf((&s0.x)[j] - mrow) * ilrow;
            p[4+j]  = __expf((&s1.x)[j] - mrow) * ilrow;
            p[8+j]  = __expf((&s2.x)[j] - mrow) * ilrow;
            p[12+j] = __expf((&s3.x)[j] - mrow) * ilrow;
        }
        #pragma unroll
        for (int j = 0; j < 8; ++j)
            As[0][skk+j][lrow] = pack_h2(p[2*j], p[2*j+1]);
    } else {
        s0 = *(const float4*)Wptr;                 // row 2kq
        s1 = *(const float4*)(Wptr + 1024);        // row 2kq+1
        s2 = *(const float4*)(Wptr + 16*1024);     // row 2(kq+8)
        s3 = *(const float4*)(Wptr + 17*1024);     // row 2(kq+8)+1
        #pragma unroll
        for (int j = 0; j < 4; ++j) {
            Ws[0][kq  ][n4*4+j] = pack_h2((&s0.x)[j], (&s1.x)[j]);
            Ws[0][kq+8][n4*4+j] = pack_h2((&s2.x)[j], (&s3.x)[j]);
        }
    }
    __syncthreads();

    for (int t = 0; t < nt; ++t) {
        const int cur = t & 1;
        if (t + 1 < nt) {
            if (isA) {
                s0 = *(const float4*)(Aptr + (t+1)*32);
                s1 = *(const float4*)(Aptr + (t+1)*32 + 4);
                s2 = *(const float4*)(Aptr + (t+1)*32 + 8);
                s3 = *(const float4*)(Aptr + (t+1)*32 + 12);
            } else {
                const float* p = Wptr + (size_t)(t+1)*32*1024;
                s0 = *(const float4*)p;
                s1 = *(const float4*)(p + 1024);
                s2 = *(const float4*)(p + 16*1024);
                s3 = *(const float4*)(p + 17*1024);
            }
        }
        #pragma unroll
        for (int ks = 0; ks < 2; ++ks) {
            const int kb = ks*8;
            unsigned af[2][4], bf[4][2];
            #pragma unroll
            for (int i = 0; i < 2; ++i) {
                int m0 = wm*32 + i*16 + qr;
                af[i][0] = As[cur][kb+qc  ][m0];
                af[i][1] = As[cur][kb+qc  ][m0+8];
                af[i][2] = As[cur][kb+qc+4][m0];
                af[i][3] = As[cur][kb+qc+4][m0+8];
            }
            #pragma unroll
            for (int j = 0; j < 4; ++j) {
                int n0 = wn*32 + j*8 + qr;
                bf[j][0] = Ws[cur][kb+qc  ][n0];
                bf[j][1] = Ws[cur][kb+qc+4][n0];
            }
            #pragma unroll
            for (int i = 0; i < 2; ++i)
                #pragma unroll
                for (int j = 0; j < 4; ++j)
                    mma_f16(acc[i][j], af[i][0], af[i][1], af[i][2], af[i][3],
                            bf[j][0], bf[j][1]);
        }
        if (t + 1 < nt) {
            const int nxt = cur ^ 1;
            if (isA) {
                float p[16];
                #pragma unroll
                for (int j = 0; j < 4; ++j) {
                    p[j]    = __expf((&s0.x)[j] - mrow) * ilrow;
                    p[4+j]  = __expf((&s1.x)[j] - mrow) * ilrow;
                    p[8+j]  = __expf((&s2.x)[j] - mrow) * ilrow;
                    p[12+j] = __expf((&s3.x)[j] - mrow) * ilrow;
                }
                #pragma unroll
                for (int j = 0; j < 8; ++j)
                    As[nxt][skk+j][lrow] = pack_h2(p[2*j], p[2*j+1]);
            } else {
                #pragma unroll
                for (int j = 0; j < 4; ++j) {
                    Ws[nxt][kq  ][n4*4+j] = pack_h2((&s0.x)[j], (&s1.x)[j]);
                    Ws[nxt][kq+8][n4*4+j] = pack_h2((&s2.x)[j], (&s3.x)[j]);
                }
            }
        }
        __syncthreads();
    }

    float* Cb = g_cat + (size_t)(b*SEQ)*1024 + head*HDIM;
    #pragma unroll
    for (int i = 0; i < 2; ++i) {
        int r0 = bm + wm*32 + i*16 + qr;
        #pragma unroll
        for (int j = 0; j < 4; ++j) {
            int c0 = bn + wn*32 + j*8 + 2*qc;
            float2 o0, o1;
            o0.x = acc[i][j][0]; o0.y = acc[i][j][1];
            o1.x = acc[i][j][2]; o1.y = acc[i][j][3];
            *(float2*)&Cb[(size_t)r0*1024 + c0]     = o0;
            *(float2*)&Cb[(size_t)(r0+8)*1024 + c0] = o1;
        }
    }
}

// ---------------- bit packing for boolean heads ----------------
__global__ void pack_bits()
{
    int gw = (blockIdx.x * blockDim.x + threadIdx.x) >> 5;
    int lane = threadIdx.x & 31;
    if (gw >= NTOK) return;
    unsigned q0 = __ballot_sync(0xffffffffu, g_qproj[(size_t)gw*PROJ + lane]       > 0.f);
    unsigned q1 = __ballot_sync(0xffffffffu, g_qproj[(size_t)gw*PROJ + 96 + lane]  > 0.f);
    unsigned k0 = __ballot_sync(0xffffffffu, g_kproj[(size_t)gw*PROJ + lane]       > 0.f);
    unsigned k1 = __ballot_sync(0xffffffffu, g_kproj[(size_t)gw*PROJ + 96 + lane]  > 0.f);
    if (lane == 0) {
        g_qbits[gw*2]   = q0; g_qbits[gw*2+1] = q1;
        g_kbits[gw*2]   = k0; g_kbits[gw*2+1] = k1;
    }
}

// ---------------- stage 1: scores (massively parallel, 64q x 64k tiles) ----
#define RE_STRIDE 34
#define TR_STRIDE 17

__global__ __launch_bounds__(256) void scores_kernel(
    const float* __restrict__ t_temp, const float* __restrict__ p_fusion)
{
    __shared__ float    qer[64*RE_STRIDE];
    __shared__ float    ker[64*RE_STRIDE];
    __shared__ __half2  qet[64*TR_STRIDE];
    __shared__ __half2  ket[64*TR_STRIDE];
    __shared__ unsigned qb[64], kb[64];

    const int k0  = blockIdx.x * 64;
    const int n0  = blockIdx.y * 64;
    const int bh  = blockIdx.z;
    const int b   = bh >> 2, head = bh & 3;
    const int tid = threadIdx.x;

    float inv_sp = 1.f;
    if (head == 1) inv_sp = 1.f / log1pf(expf(t_temp[0]));
    float fw0 = 0.f, fw1 = 0.f, fw2 = 0.f;
    if (head == 3) {
        float p0 = p_fusion[0], p1 = p_fusion[1], p2 = p_fusion[2];
        float mx = fmaxf(p0, fmaxf(p1, p2));
        float e0 = expf(p0-mx), e1 = expf(p1-mx), e2 = expf(p2-mx);
        float inv = 1.f/(e0+e1+e2);
        fw0 = e0*inv; fw1 = e1*inv; fw2 = e2*inv;
    }

    if (head == 0) {
        if (tid < 64)       qb[tid]    = g_qbits[(b*SEQ + n0 + tid)*2];
        else if (tid < 128) kb[tid-64] = g_kbits[(b*SEQ + k0 + tid-64)*2];
    } else if (head == 1) {
        for (int j = tid; j < 1024; j += 256) {
            int t = j >> 4, m = j & 15;
            const float* bq_ = &g_qproj[(size_t)(b*SEQ + n0 + t)*PROJ];
            const float* bk_ = &g_kproj[(size_t)(b*SEQ + k0 + t)*PROJ];
            qet[t*TR_STRIDE+m] = __floats2half2_rn(bq_[32+2*m], bq_[33+2*m]);
            ket[t*TR_STRIDE+m] = __floats2half2_rn(bk_[32+2*m], bk_[33+2*m]);
        }
    } else if (head == 2) {
        for (int j = tid; j < 2048; j += 256) {
            int t = j >> 5, m = j & 31;
            qer[t*RE_STRIDE+m] = g_qproj[(size_t)(b*SEQ + n0 + t)*PROJ + 64 + m];
            ker[t*RE_STRIDE+m] = g_kproj[(size_t)(b*SEQ + k0 + t)*PROJ + 64 + m];
        }
    } else {
        if (tid < 64)       qb[tid]    = g_qbits[(b*SEQ + n0 + tid)*2 + 1];
        else if (tid < 128) kb[tid-64] = g_kbits[(b*SEQ + k0 + tid-64)*2 + 1];
        for (int j = tid; j < 1024; j += 256) {
            int t = j >> 4, m = j & 15;
            const float* bq_ = &g_qproj[(size_t)(b*SEQ + n0 + t)*PROJ];
            const float* bk_ = &g_kproj[(size_t)(b*SEQ + k0 + t)*PROJ];
            qet[t*TR_STRIDE+m] = __floats2half2_rn(bq_[128+2*m], bq_[129+2*m]);
            ket[t*TR_STRIDE+m] = __floats2half2_rn(bk_[128+2*m], bk_[129+2*m]);
        }
        for (int j = tid; j < 2048; j += 256) {
            int t = j >> 5, m = j & 31;
            qer[t*RE_STRIDE+m] = g_qproj[(size_t)(b*SEQ + n0 + t)*PROJ + 160 + m];
            ker[t*RE_STRIDE+m] = g_kproj[(size_t)(b*SEQ + k0 + t)*PROJ + 160 + m];
        }
    }
    __syncthreads();

    const int kk    = tid & 63;
    const int qbase = (tid >> 6) * 16;
    float* Sout = g_S + ((size_t)bh << 20) + (size_t)(n0 + qbase)*1024 + k0 + kk;

    if (head == 0) {
        unsigned kr = kb[kk];
        #pragma unroll
        for (int i = 0; i < 16; ++i) {
            int p = __popc(qb[qbase+i] ^ kr);
            Sout[(size_t)i*1024] = (1.f - p*(1.f/32.f)) * SCALEF;
        }
    } else if (head == 1) {
        __half2 kr[16];
        const __half2* krow = &ket[kk*TR_STRIDE];
        #pragma unroll
        for (int m = 0; m < 16; ++m) kr[m] = krow[m];
        #pragma unroll 4
        for (int i = 0; i < 16; ++i) {
            const __half2* qe = &qet[(qbase+i)*TR_STRIDE];
            __half2 mnA = __hadd2(qe[0], kr[0]);
            __half2 mnB = __hadd2(qe[1], kr[1]);
            #pragma unroll
            for (int m = 2; m < 16; m += 2) {
                mnA = __hmin2(mnA, __hadd2(qe[m],   kr[m]));
                mnB = __hmin2(mnB, __hadd2(qe[m+1], kr[m+1]));
            }
            __half2 mn = __hmin2(mnA, mnB);
            float mnf = fminf(__low2float(mn), __high2float(mn));
            Sout[(size_t)i*1024] = -mnf * inv_sp;
        }
    } else if (head == 2) {
        float krr[32];
        const float* krow = &ker[kk*RE_STRIDE];
        #pragma unroll
        for (int m = 0; m < 32; ++m) krr[m] = krow[m];
        #pragma unroll 4
        for (int i = 0; i < 16; ++i) {
            const float* qe = &qer[(qbase+i)*RE_STRIDE];
            float da = 0.f, db = 0.f;
            #pragma unroll
            for (int m = 0; m < 32; m += 2) {
                da = fmaf(qe[m],   krr[m],   da);
                db = fmaf(qe[m+1], krr[m+1], db);
            }
            Sout[(size_t)i*1024] = (da + db) * SCALEF;
        }
    } else {
        __half2 krt[16];
        float krr[32];
        const __half2* ktrow = &ket[kk*TR_STRIDE];
        const float* krrow = &ker[kk*RE_STRIDE];
        #pragma unroll
        for (int m = 0; m < 16; ++m) krt[m] = ktrow[m];
        #pragma unroll
        for (int m = 0; m < 32; ++m) krr[m] = krrow[m];
        unsigned kr = kb[kk];
        #pragma unroll 2
        for (int i = 0; i < 16; ++i) {
            const __half2* qe = &qet[(qbase+i)*TR_STRIDE];
            const float* qf  = &qer[(qbase+i)*RE_STRIDE];
            __half2 mnA = __hadd2(qe[0], krt[0]);
            __half2 mnB = __hadd2(qe[1], krt[1]);
            float da = 0.f, db = 0.f;
            #pragma unroll
            for (int m = 2; m < 16; m += 2) {
                mnA = __hmin2(mnA, __hadd2(qe[m],   krt[m]));
                mnB = __hmin2(mnB, __hadd2(qe[m+1], krt[m+1]));
            }
            #pragma unroll
            for (int m = 0; m < 32; m += 2) {
                da = fmaf(qf[m],   krr[m],   da);
                db = fmaf(qf[m+1], krr[m+1], db);
            }
            __half2 mn = __hmin2(mnA, mnB);
            float mnf = fminf(__low2float(mn), __high2float(mn));
            float simb = 1.f - __popc(qb[qbase+i] ^ kr)*(1.f/32.f);
            Sout[(size_t)i*1024] = (fw0*simb - fw1*mnf + fw2*(da + db)) * SCALEF;
        }
    }
}

// ---------------- stage 2: row softmax stats (1 warp / row) ----------------
__device__ __forceinline__ float wredmax(float v) {
    #pragma unroll
    for (int o = 16; o; o >>= 1) v = fmaxf(v, __shfl_xor_sync(0xffffffffu, v, o));
    return v;
}
__device__ __forceinline__ float wredsum(float v) {
    #pragma unroll
    for (int o = 16; o; o >>= 1) v += __shfl_xor_sync(0xffffffffu, v, o);
    return v;
}

__global__ __launch_bounds__(256) void stats_kernel()
{
    int gw   = (blockIdx.x * blockDim.x + threadIdx.x) >> 5;  // row 0..8191
    int lane = threadIdx.x & 31;
    const float4* srow = (const float4*)(g_S + ((size_t)gw << 10));
    float4 v[8];
    float mx = -INFINITY;
    #pragma unroll
    for (int j = 0; j < 8; ++j) {
        v[j] = srow[j*32 + lane];
        mx = fmaxf(mx, fmaxf(fmaxf(v[j].x, v[j].y), fmaxf(v[j].z, v[j].w)));
    }
    mx = wredmax(mx);
    float s = 0.f;
    #pragma unroll
    for (int j = 0; j < 8; ++j)
        s += __expf(v[j].x-mx) + __expf(v[j].y-mx) + __expf(v[j].z-mx) + __expf(v[j].w-mx);
    s = wredsum(s);
    if (lane == 0) { g_m[gw] = mx; g_il[gw] = 1.f/s; }
}

// ---------------- host launch ----------------
extern "C" void kernel_launch(void* const* d_in, const int* in_sizes, int n_in,
                              void* d_out, int out_size)
{
    const float* Q        = (const float*)d_in[0];
    const float* K        = (const float*)d_in[1];
    const float* V        = (const float*)d_in[2];
    const float* bq_w     = (const float*)d_in[3];
    const float* bq_b     = (const float*)d_in[4];
    const float* bk_w     = (const float*)d_in[5];
    const float* bk_b     = (const float*)d_in[6];
    const float* b_v      = (const float*)d_in[7];
    const float* tq_w     = (const float*)d_in[8];
    const float* tq_b     = (const float*)d_in[9];
    const float* tk_w     = (const float*)d_in[10];
    const float* tk_b     = (const float*)d_in[11];
    const float* t_v      = (const float*)d_in[12];
    const float* t_temp   = (const float*)d_in[13];
    const float* rq_w     = (const float*)d_in[14];
    const float* rq_b     = (const float*)d_in[15];
    const float* rk_w     = (const float*)d_in[16];
    const float* rk_b     = (const float*)d_in[17];
    const float* r_v      = (const float*)d_in[18];
    const float* pq_w     = (const float*)d_in[19];
    const float* pq_b     = (const float*)d_in[20];
    const float* pk_w     = (const float*)d_in[21];
    const float* pk_b     = (const float*)d_in[22];
    const float* p_v      = (const float*)d_in[23];
    const float* p_fusion = (const float*)d_in[24];
    const float* out_w    = (const float*)d_in[25];
    const float* out_b    = (const float*)d_in[26];
    float* out = (float*)d_out;

    void *pVp, *pcat;
    cudaGetSymbolAddress(&pVp,  g_Vp);
    cudaGetSymbolAddress(&pcat, g_cat);

    // fused front-end: V-proj (fp16 mma) + QK-proj (exact fp32), one launch
    fused_qkv<<<320, 512>>>(V, b_v, t_v, r_v, p_v, Q, K,
                            bq_w, tq_w, rq_w, pq_w,
                            bk_w, tk_w, rk_w, pk_w,
                            bq_b, tq_b, rq_b, pq_b,
                            bk_b, tk_b, rk_b, pk_b,
                            (float*)pVp);

    pack_bits<<<NTOK*32/256, 256>>>();

    // stage 1: all scores
    scores_kernel<<<dim3(16, 16, 8), 256>>>(t_temp, p_fusion);

    // stage 2: exact softmax stats
    stats_kernel<<<1024, 256>>>();

    // stage 3: exp-weighted PV fp16 tensor-core GEMM -> g_cat
    gemm_pv512<<<dim3(2, 8, 8), 512>>>();

    // output projection (fp16 tensor cores)
    gemm_tc512<<<dim3(8, 16), 512>>>((const float*)pcat, out_w, out_b,
                                     out, DIM, DIM);
}

// round 11
// speedup vs baseline: 1.1666x; 1.1666x over previous
#include <cuda_runtime.h>
#include <cuda_fp16.h>
#include <math.h>

// ---------------- problem constants ----------------
#define BATCH 2
#define SEQ   1024
#define DIM   1024
#define HDIM  256
#define MBITS 32
#define NTOK  (BATCH*SEQ)     // 2048
#define PROJ  192             // 6 groups x 32
#define SCALEF 0.17677669529663687f  // 1/sqrt(32)

// ---------------- device scratch (static, no allocs) ----------------
__device__ float    g_qproj[NTOK*PROJ];
__device__ float    g_kproj[NTOK*PROJ];
__device__ unsigned g_qbits[NTOK*2];
__device__ unsigned g_kbits[NTOK*2];
__device__ float    g_Vp[NTOK*4*HDIM];
__device__ float    g_cat[NTOK*4*HDIM];
__device__ float    g_S[8u*1024u*1024u];   // [b*4+head][q][k] scores, 32MB
__device__ float    g_m[8*1024];           // row max
__device__ float    g_il[8*1024];          // 1/row sumexp

// ---------------- fp16 mma helpers ----------------
__device__ __forceinline__ unsigned pack_h2(float lo, float hi) {
    __half2 h = __floats2half2_rn(lo, hi);
    return *(unsigned*)&h;
}
__device__ __forceinline__ void mma_f16(float c[4],
    unsigned a0, unsigned a1, unsigned a2, unsigned a3,
    unsigned b0, unsigned b1)
{
    asm("mma.sync.aligned.m16n8k16.row.col.f32.f16.f16.f32 "
        "{%0,%1,%2,%3},{%4,%5,%6,%7},{%8,%9},{%0,%1,%2,%3};"
        : "+f"(c[0]), "+f"(c[1]), "+f"(c[2]), "+f"(c[3])
        : "r"(a0), "r"(a1), "r"(a2), "r"(a3), "r"(b0), "r"(b1));
}

// ---------------- 512-thread fp16 GEMM core: 128x128 tile, BK=32 ----------
// A[M,K] row-major fp32, W[N,K] row-major fp32 (B^T), C row-major fp32.
__device__ __forceinline__ void tc512h_core(
    const float* __restrict__ A, const float* __restrict__ W,
    const float* __restrict__ bias, float* __restrict__ C,
    int K, int ldc, int bm, int bn)
{
    __shared__ unsigned As[2][16][136];
    __shared__ unsigned Ws[2][16][136];

    const int tid = threadIdx.x;
    const int w = tid >> 5, lane = tid & 31;
    const int wm = w >> 2, wn = w & 3;          // 4x4 warp grid, 32x32 tiles
    const int qr = lane >> 2, qc = lane & 3;

    const bool isA = tid < 256;
    const int st = isA ? tid : tid - 256;
    const int srow = st >> 1, sk16 = (st & 1) * 16, skk = (st & 1) * 8;
    const float* Sptr = isA ? A + (size_t)(bm + srow)*K + sk16
                            : W + (size_t)(bn + srow)*K + sk16;

    float acc[2][4][4];
    #pragma unroll
    for (int i = 0; i < 2; ++i)
        #pragma unroll
        for (int j = 0; j < 4; ++j)
            #pragma unroll
            for (int r = 0; r < 4; ++r) acc[i][j][r] = 0.f;

    const int nt = K >> 5;
    float4 s0 = *(const float4*)Sptr;
    float4 s1 = *(const float4*)(Sptr + 4);
    float4 s2 = *(const float4*)(Sptr + 8);
    float4 s3 = *(const float4*)(Sptr + 12);
    {
        unsigned* dst = isA ? &As[0][0][0] : &Ws[0][0][0];
        dst[(skk+0)*136+srow] = pack_h2(s0.x, s0.y);
        dst[(skk+1)*136+srow] = pack_h2(s0.z, s0.w);
        dst[(skk+2)*136+srow] = pack_h2(s1.x, s1.y);
        dst[(skk+3)*136+srow] = pack_h2(s1.z, s1.w);
        dst[(skk+4)*136+srow] = pack_h2(s2.x, s2.y);
        dst[(skk+5)*136+srow] = pack_h2(s2.z, s2.w);
        dst[(skk+6)*136+srow] = pack_h2(s3.x, s3.y);
        dst[(skk+7)*136+srow] = pack_h2(s3.z, s3.w);
    }
    __syncthreads();

    for (int t = 0; t < nt; ++t) {
        const int cur = t & 1;
        if (t + 1 < nt) {
            s0 = *(const float4*)(Sptr + (t+1)*32);
            s1 = *(const float4*)(Sptr + (t+1)*32 + 4);
            s2 = *(const float4*)(Sptr + (t+1)*32 + 8);
            s3 = *(const float4*)(Sptr + (t+1)*32 + 12);
        }
        #pragma unroll
        for (int ks = 0; ks < 2; ++ks) {
            const int kb = ks*8;
            unsigned af[2][4], bf[4][2];
            #pragma unroll
            for (int i = 0; i < 2; ++i) {
                int m0 = wm*32 + i*16 + qr;
                af[i][0] = As[cur][kb+qc  ][m0];
                af[i][1] = As[cur][kb+qc  ][m0+8];
                af[i][2] = As[cur][kb+qc+4][m0];
                af[i][3] = As[cur][kb+qc+4][m0+8];
            }
            #pragma unroll
            for (int j = 0; j < 4; ++j) {
                int n0 = wn*32 + j*8 + qr;
                bf[j][0] = Ws[cur][kb+qc  ][n0];
                bf[j][1] = Ws[cur][kb+qc+4][n0];
            }
            #pragma unroll
            for (int i = 0; i < 2; ++i)
                #pragma unroll
                for (int j = 0; j < 4; ++j)
                    mma_f16(acc[i][j], af[i][0], af[i][1], af[i][2], af[i][3],
                            bf[j][0], bf[j][1]);
        }
        if (t + 1 < nt) {
            const int nxt = cur ^ 1;
            unsigned* dst = isA ? &As[nxt][0][0] : &Ws[nxt][0][0];
            dst[(skk+0)*136+srow] = pack_h2(s0.x, s0.y);
            dst[(skk+1)*136+srow] = pack_h2(s0.z, s0.w);
            dst[(skk+2)*136+srow] = pack_h2(s1.x, s1.y);
            dst[(skk+3)*136+srow] = pack_h2(s1.z, s1.w);
            dst[(skk+4)*136+srow] = pack_h2(s2.x, s2.y);
            dst[(skk+5)*136+srow] = pack_h2(s2.z, s2.w);
            dst[(skk+6)*136+srow] = pack_h2(s3.x, s3.y);
            dst[(skk+7)*136+srow] = pack_h2(s3.z, s3.w);
        }
        __syncthreads();
    }

    #pragma unroll
    for (int i = 0; i < 2; ++i) {
        int r0 = bm + wm*32 + i*16 + qr;
        #pragma unroll
        for (int j = 0; j < 4; ++j) {
            int c0 = bn + wn*32 + j*8 + 2*qc;
            float bx = 0.f, by = 0.f;
            if (bias) { bx = bias[c0]; by = bias[c0+1]; }
            float2 o0, o1;
            o0.x = acc[i][j][0] + bx; o0.y = acc[i][j][1] + by;
            o1.x = acc[i][j][2] + bx; o1.y = acc[i][j][3] + by;
            *(float2*)&C[(size_t)r0*ldc + c0]     = o0;
            *(float2*)&C[(size_t)(r0+8)*ldc + c0] = o1;
        }
    }
}

// ---------------- fp32 QK projection GEMM: 64x64 tiles, direct weights ----
__global__ __launch_bounds__(256) void gemm_qk(
    const float* __restrict__ Qin, const float* __restrict__ Kin,
    const float* __restrict__ bq_w, const float* __restrict__ tq_w,
    const float* __restrict__ rq_w, const float* __restrict__ pq_w,
    const float* __restrict__ bk_w, const float* __restrict__ tk_w,
    const float* __restrict__ rk_w, const float* __restrict__ pk_w,
    const float* __restrict__ bq_b, const float* __restrict__ tq_b,
    const float* __restrict__ rq_b, const float* __restrict__ pq_b,
    const float* __restrict__ bk_b, const float* __restrict__ tk_b,
    const float* __restrict__ rk_b, const float* __restrict__ pk_b)
{
    __shared__ __align__(16) float As[2][8][68];
    __shared__ __align__(16) float Ws[2][8][68];

    const int z = blockIdx.z;
    const float* A = z ? Kin : Qin;
    float*       C = z ? g_kproj : g_qproj;
    const float* wsrc[6];
    const float* bsrc[6];
    if (z) {
        wsrc[0]=bk_w; wsrc[1]=tk_w; wsrc[2]=rk_w;
        wsrc[3]=pk_w; wsrc[4]=pk_w+(size_t)32*DIM; wsrc[5]=pk_w+(size_t)64*DIM;
        bsrc[0]=bk_b; bsrc[1]=tk_b; bsrc[2]=rk_b;
        bsrc[3]=pk_b; bsrc[4]=pk_b+32; bsrc[5]=pk_b+64;
    } else {
        wsrc[0]=bq_w; wsrc[1]=tq_w; wsrc[2]=rq_w;
        wsrc[3]=pq_w; wsrc[4]=pq_w+(size_t)32*DIM; wsrc[5]=pq_w+(size_t)64*DIM;
        bsrc[0]=bq_b; bsrc[1]=tq_b; bsrc[2]=rq_b;
        bsrc[3]=pq_b; bsrc[4]=pq_b+32; bsrc[5]=pq_b+64;
    }

    const int bm = blockIdx.y * 64, bn = blockIdx.x * 64;
    const int tid = threadIdx.x;
    const int tx = tid & 15, ty = tid >> 4;

    const bool isA = tid < 128;
    const int st = isA ? tid : tid - 128;
    const int srow = st >> 1, sc4 = (st & 1) * 4;
    const float* Sptr;
    if (isA) Sptr = A + (size_t)(bm + srow)*DIM + sc4;
    else {
        int wr = bn + srow;
        Sptr = wsrc[wr >> 5] + (size_t)(wr & 31)*DIM + sc4;
    }

    float acc[4][4];
    #pragma unroll
    for (int i = 0; i < 4; ++i)
        #pragma unroll
        for (int j = 0; j < 4; ++j) acc[i][j] = 0.f;

    const int nt = DIM >> 3;  // 128
    float4 sreg = *(const float4*)Sptr;
    #pragma unroll
    for (int j = 0; j < 4; ++j) {
        if (isA) As[0][sc4+j][srow] = (&sreg.x)[j];
        else     Ws[0][sc4+j][srow] = (&sreg.x)[j];
    }
    __syncthreads();

    for (int t = 0; t < nt; ++t) {
        const int cur = t & 1;
        if (t + 1 < nt) sreg = *(const float4*)(Sptr + (t+1)*8);
        #pragma unroll
        for (int kk = 0; kk < 8; ++kk) {
            float4 a4 = *(const float4*)&As[cur][kk][ty*4];
            float4 b4 = *(const float4*)&Ws[cur][kk][tx*4];
            const float* a = &a4.x;
            const float* b = &b4.x;
            #pragma unroll
            for (int i = 0; i < 4; ++i)
                #pragma unroll
                for (int j = 0; j < 4; ++j)
                    acc[i][j] += a[i]*b[j];
        }
        if (t + 1 < nt) {
            const int nxt = cur ^ 1;
            #pragma unroll
            for (int j = 0; j < 4; ++j) {
                if (isA) As[nxt][sc4+j][srow] = (&sreg.x)[j];
                else     Ws[nxt][sc4+j][srow] = (&sreg.x)[j];
            }
        }
        __syncthreads();
    }

    const int col = bn + tx*4;
    const float* bb = bsrc[col >> 5] + (col & 31);
    #pragma unroll
    for (int i = 0; i < 4; ++i) {
        int row = bm + ty*4 + i;
        float4 o;
        o.x = acc[i][0] + bb[0];
        o.y = acc[i][1] + bb[1];
        o.z = acc[i][2] + bb[2];
        o.w = acc[i][3] + bb[3];
        *(float4*)&C[(size_t)row*PROJ + col] = o;
    }
}

// out-proj: C[2048,1024] = cat * out_w^T + out_b
__global__ __launch_bounds__(512) void gemm_tc512(
    const float* __restrict__ A, const float* __restrict__ W,
    const float* __restrict__ bias, float* __restrict__ C,
    int K, int ldc)
{
    tc512h_core(A, W, bias, C, K, ldc, blockIdx.y*128, blockIdx.x*128);
}

// V projection per head (z selects head weight), strided output into g_Vp
__global__ __launch_bounds__(512) void gemm_tcv512(
    const float* __restrict__ V,
    const float* __restrict__ w0, const float* __restrict__ w1,
    const float* __restrict__ w2, const float* __restrict__ w3,
    float* __restrict__ C)
{
    const float* W = (blockIdx.z == 0) ? w0 : (blockIdx.z == 1) ? w1
                   : (blockIdx.z == 2) ? w2 : w3;
    tc512h_core(V, W, nullptr, C + blockIdx.z*HDIM,
                DIM, 4*HDIM, blockIdx.y*128, blockIdx.x*128);
}

// ---------------- PV GEMM, fp16 mma, BK=32, fused exp weighting -----------
__global__ __launch_bounds__(512) void gemm_pv512()
{
    __shared__ unsigned As[2][16][136];
    __shared__ unsigned Ws[2][16][136];

    const int bh = blockIdx.z, b = bh >> 2, head = bh & 3;
    const int bm = blockIdx.y * 128, bn = blockIdx.x * 128;
    const int tid = threadIdx.x;
    const int w = tid >> 5, lane = tid & 31;
    const int wm = w >> 2, wn = w & 3;
    const int qr = lane >> 2, qc = lane & 3;

    const bool isA = tid < 256;
    const int st = isA ? tid : tid - 256;
    const int lrow = st >> 1, sk16 = (st & 1) * 16, skk = (st & 1) * 8;
    const float* Aptr = g_S + ((size_t)bh << 20) + (size_t)(bm + lrow)*1024 + sk16;
    const float mrow  = g_m [bh*1024 + bm + lrow];
    const float ilrow = g_il[bh*1024 + bm + lrow];
    const int kq = st >> 5, n4 = st & 31;
    const float* Wptr = g_Vp + (size_t)(b*SEQ + 2*kq)*1024 + head*HDIM + bn + n4*4;

    float acc[2][4][4];
    #pragma unroll
    for (int i = 0; i < 2; ++i)
        #pragma unroll
        for (int j = 0; j < 4; ++j)
            #pragma unroll
            for (int r = 0; r < 4; ++r) acc[i][j][r] = 0.f;

    const int nt = 32;   // K=1024, BK=32
    float4 s0, s1, s2, s3;
    if (isA) {
        s0 = *(const float4*)Aptr;       s1 = *(const float4*)(Aptr + 4);
        s2 = *(const float4*)(Aptr + 8); s3 = *(const float4*)(Aptr + 12);
        float p[16];
        #pragma unroll
        for (int j = 0; j < 4; ++j) {
            p[j]    = __expf((&s0.x)[j] - mrow) * ilrow;
            p[4+j]  = __expf((&s1.x)[j] - mrow) * ilrow;
            p[8+j]  = __expf((&s2.x)[j] - mrow) * ilrow;
            p[12+j] = __expf((&s3.x)[j] - mrow) * ilrow;
        }
        #pragma unroll
        for (int j = 0; j < 8; ++j)
            As[0][skk+j][lrow] = pack_h2(p[2*j], p[2*j+1]);
    } else {
        s0 = *(const float4*)Wptr;
        s1 = *(const float4*)(Wptr + 1024);
        s2 = *(const float4*)(Wptr + 16*1024);
        s3 = *(const float4*)(Wptr + 17*1024);
        #pragma unroll
        for (int j = 0; j < 4; ++j) {
            Ws[0][kq  ][n4*4+j] = pack_h2((&s0.x)[j], (&s1.x)[j]);
            Ws[0][kq+8][n4*4+j] = pack_h2((&s2.x)[j], (&s3.x)[j]);
        }
    }
    __syncthreads();

    for (int t = 0; t < nt; ++t) {
        const int cur = t & 1;
        if (t + 1 < nt) {
            if (isA) {
                s0 = *(const float4*)(Aptr + (t+1)*32);
                s1 = *(const float4*)(Aptr + (t+1)*32 + 4);
                s2 = *(const float4*)(Aptr + (t+1)*32 + 8);
                s3 = *(const float4*)(Aptr + (t+1)*32 + 12);
            } else {
                const float* p = Wptr + (size_t)(t+1)*32*1024;
                s0 = *(const float4*)p;
                s1 = *(const float4*)(p + 1024);
                s2 = *(const float4*)(p + 16*1024);
                s3 = *(const float4*)(p + 17*1024);
            }
        }
        #pragma unroll
        for (int ks = 0; ks < 2; ++ks) {
            const int kb = ks*8;
            unsigned af[2][4], bf[4][2];
            #pragma unroll
            for (int i = 0; i < 2; ++i) {
                int m0 = wm*32 + i*16 + qr;
                af[i][0] = As[cur][kb+qc  ][m0];
                af[i][1] = As[cur][kb+qc  ][m0+8];
                af[i][2] = As[cur][kb+qc+4][m0];
                af[i][3] = As[cur][kb+qc+4][m0+8];
            }
            #pragma unroll
            for (int j = 0; j < 4; ++j) {
                int n0 = wn*32 + j*8 + qr;
                bf[j][0] = Ws[cur][kb+qc  ][n0];
                bf[j][1] = Ws[cur][kb+qc+4][n0];
            }
            #pragma unroll
            for (int i = 0; i < 2; ++i)
                #pragma unroll
                for (int j = 0; j < 4; ++j)
                    mma_f16(acc[i][j], af[i][0], af[i][1], af[i][2], af[i][3],
                            bf[j][0], bf[j][1]);
        }
        if (t + 1 < nt) {
            const int nxt = cur ^ 1;
            if (isA) {
                float p[16];
                #pragma unroll
                for (int j = 0; j < 4; ++j) {
                    p[j]    = __expf((&s0.x)[j] - mrow) * ilrow;
                    p[4+j]  = __expf((&s1.x)[j] - mrow) * ilrow;
                    p[8+j]  = __expf((&s2.x)[j] - mrow) * ilrow;
                    p[12+j] = __expf((&s3.x)[j] - mrow) * ilrow;
                }
                #pragma unroll
                for (int j = 0; j < 8; ++j)
                    As[nxt][skk+j][lrow] = pack_h2(p[2*j], p[2*j+1]);
            } else {
                #pragma unroll
                for (int j = 0; j < 4; ++j) {
                    Ws[nxt][kq  ][n4*4+j] = pack_h2((&s0.x)[j], (&s1.x)[j]);
                    Ws[nxt][kq+8][n4*4+j] = pack_h2((&s2.x)[j], (&s3.x)[j]);
                }
            }
        }
        __syncthreads();
    }

    float* Cb = g_cat + (size_t)(b*SEQ)*1024 + head*HDIM;
    #pragma unroll
    for (int i = 0; i < 2; ++i) {
        int r0 = bm + wm*32 + i*16 + qr;
        #pragma unroll
        for (int j = 0; j < 4; ++j) {
            int c0 = bn + wn*32 + j*8 + 2*qc;
            float2 o0, o1;
            o0.x = acc[i][j][0]; o0.y = acc[i][j][1];
            o1.x = acc[i][j][2]; o1.y = acc[i][j][3];
            *(float2*)&Cb[(size_t)r0*1024 + c0]     = o0;
            *(float2*)&Cb[(size_t)(r0+8)*1024 + c0] = o1;
        }
    }
}

// ---------------- bit packing for boolean heads ----------------
__global__ void pack_bits()
{
    int gw = (blockIdx.x * blockDim.x + threadIdx.x) >> 5;
    int lane = threadIdx.x & 31;
    if (gw >= NTOK) return;
    unsigned q0 = __ballot_sync(0xffffffffu, g_qproj[(size_t)gw*PROJ + lane]       > 0.f);
    unsigned q1 = __ballot_sync(0xffffffffu, g_qproj[(size_t)gw*PROJ + 96 + lane]  > 0.f);
    unsigned k0 = __ballot_sync(0xffffffffu, g_kproj[(size_t)gw*PROJ + lane]       > 0.f);
    unsigned k1 = __ballot_sync(0xffffffffu, g_kproj[(size_t)gw*PROJ + 96 + lane]  > 0.f);
    if (lane == 0) {
        g_qbits[gw*2]   = q0; g_qbits[gw*2+1] = q1;
        g_kbits[gw*2]   = k0; g_kbits[gw*2+1] = k1;
    }
}

// ---------------- stage 1: scores (massively parallel, 64q x 64k tiles) ----
#define RE_STRIDE 34
#define TR_STRIDE 17

__global__ __launch_bounds__(256) void scores_kernel(
    const float* __restrict__ t_temp, const float* __restrict__ p_fusion)
{
    __shared__ float    qer[64*RE_STRIDE];
    __shared__ float    ker[64*RE_STRIDE];
    __shared__ __half2  qet[64*TR_STRIDE];
    __shared__ __half2  ket[64*TR_STRIDE];
    __shared__ unsigned qb[64], kb[64];

    const int k0  = blockIdx.x * 64;
    const int n0  = blockIdx.y * 64;
    const int bh  = blockIdx.z;
    const int b   = bh >> 2, head = bh & 3;
    const int tid = threadIdx.x;

    float inv_sp = 1.f;
    if (head == 1) inv_sp = 1.f / log1pf(expf(t_temp[0]));
    float fw0 = 0.f, fw1 = 0.f, fw2 = 0.f;
    if (head == 3) {
        float p0 = p_fusion[0], p1 = p_fusion[1], p2 = p_fusion[2];
        float mx = fmaxf(p0, fmaxf(p1, p2));
        float e0 = expf(p0-mx), e1 = expf(p1-mx), e2 = expf(p2-mx);
        float inv = 1.f/(e0+e1+e2);
        fw0 = e0*inv; fw1 = e1*inv; fw2 = e2*inv;
    }

    if (head == 0) {
        if (tid < 64)       qb[tid]    = g_qbits[(b*SEQ + n0 + tid)*2];
        else if (tid < 128) kb[tid-64] = g_kbits[(b*SEQ + k0 + tid-64)*2];
    } else if (head == 1) {
        for (int j = tid; j < 1024; j += 256) {
            int t = j >> 4, m = j & 15;
            const float* bq_ = &g_qproj[(size_t)(b*SEQ + n0 + t)*PROJ];
            const float* bk_ = &g_kproj[(size_t)(b*SEQ + k0 + t)*PROJ];
            qet[t*TR_STRIDE+m] = __floats2half2_rn(bq_[32+2*m], bq_[33+2*m]);
            ket[t*TR_STRIDE+m] = __floats2half2_rn(bk_[32+2*m], bk_[33+2*m]);
        }
    } else if (head == 2) {
        for (int j = tid; j < 2048; j += 256) {
            int t = j >> 5, m = j & 31;
            qer[t*RE_STRIDE+m] = g_qproj[(size_t)(b*SEQ + n0 + t)*PROJ + 64 + m];
            ker[t*RE_STRIDE+m] = g_kproj[(size_t)(b*SEQ + k0 + t)*PROJ + 64 + m];
        }
    } else {
        if (tid < 64)       qb[tid]    = g_qbits[(b*SEQ + n0 + tid)*2 + 1];
        else if (tid < 128) kb[tid-64] = g_kbits[(b*SEQ + k0 + tid-64)*2 + 1];
        for (int j = tid; j < 1024; j += 256) {
            int t = j >> 4, m = j & 15;
            const float* bq_ = &g_qproj[(size_t)(b*SEQ + n0 + t)*PROJ];
            const float* bk_ = &g_kproj[(size_t)(b*SEQ + k0 + t)*PROJ];
            qet[t*TR_STRIDE+m] = __floats2half2_rn(bq_[128+2*m], bq_[129+2*m]);
            ket[t*TR_STRIDE+m] = __floats2half2_rn(bk_[128+2*m], bk_[129+2*m]);
        }
        for (int j = tid; j < 2048; j += 256) {
            int t = j >> 5, m = j & 31;
            qer[t*RE_STRIDE+m] = g_qproj[(size_t)(b*SEQ + n0 + t)*PROJ + 160 + m];
            ker[t*RE_STRIDE+m] = g_kproj[(size_t)(b*SEQ + k0 + t)*PROJ + 160 + m];
        }
    }
    __syncthreads();

    const int kk    = tid & 63;
    const int qbase = (tid >> 6) * 16;
    float* Sout = g_S + ((size_t)bh << 20) + (size_t)(n0 + qbase)*1024 + k0 + kk;

    if (head == 0) {
        unsigned kr = kb[kk];
        #pragma unroll
        for (int i = 0; i < 16; ++i) {
            int p = __popc(qb[qbase+i] ^ kr);
            Sout[(size_t)i*1024] = (1.f - p*(1.f/32.f)) * SCALEF;
        }
    } else if (head == 1) {
        __half2 kr[16];
        const __half2* krow = &ket[kk*TR_STRIDE];
        #pragma unroll
        for (int m = 0; m < 16; ++m) kr[m] = krow[m];
        #pragma unroll 4
        for (int i = 0; i < 16; ++i) {
            const __half2* qe = &qet[(qbase+i)*TR_STRIDE];
            __half2 mnA = __hadd2(qe[0], kr[0]);
            __half2 mnB = __hadd2(qe[1], kr[1]);
            #pragma unroll
            for (int m = 2; m < 16; m += 2) {
                mnA = __hmin2(mnA, __hadd2(qe[m],   kr[m]));
                mnB = __hmin2(mnB, __hadd2(qe[m+1], kr[m+1]));
            }
            __half2 mn = __hmin2(mnA, mnB);
            float mnf = fminf(__low2float(mn), __high2float(mn));
            Sout[(size_t)i*1024] = -mnf * inv_sp;
        }
    } else if (head == 2) {
        float krr[32];
        const float* krow = &ker[kk*RE_STRIDE];
        #pragma unroll
        for (int m = 0; m < 32; ++m) krr[m] = krow[m];
        #pragma unroll 4
        for (int i = 0; i < 16; ++i) {
            const float* qe = &qer[(qbase+i)*RE_STRIDE];
            float da = 0.f, db = 0.f;
            #pragma unroll
            for (int m = 0; m < 32; m += 2) {
                da = fmaf(qe[m],   krr[m],   da);
                db = fmaf(qe[m+1], krr[m+1], db);
            }
            Sout[(size_t)i*1024] = (da + db) * SCALEF;
        }
    } else {
        __half2 krt[16];
        float krr[32];
        const __half2* ktrow = &ket[kk*TR_STRIDE];
        const float* krrow = &ker[kk*RE_STRIDE];
        #pragma unroll
        for (int m = 0; m < 16; ++m) krt[m] = ktrow[m];
        #pragma unroll
        for (int m = 0; m < 32; ++m) krr[m] = krrow[m];
        unsigned kr = kb[kk];
        #pragma unroll 2
        for (int i = 0; i < 16; ++i) {
            const __half2* qe = &qet[(qbase+i)*TR_STRIDE];
            const float* qf  = &qer[(qbase+i)*RE_STRIDE];
            __half2 mnA = __hadd2(qe[0], krt[0]);
            __half2 mnB = __hadd2(qe[1], krt[1]);
            float da = 0.f, db = 0.f;
            #pragma unroll
            for (int m = 2; m < 16; m += 2) {
                mnA = __hmin2(mnA, __hadd2(qe[m],   krt[m]));
                mnB = __hmin2(mnB, __hadd2(qe[m+1], krt[m+1]));
            }
            #pragma unroll
            for (int m = 0; m < 32; m += 2) {
                da = fmaf(qf[m],   krr[m],   da);
                db = fmaf(qf[m+1], krr[m+1], db);
            }
            __half2 mn = __hmin2(mnA, mnB);
            float mnf = fminf(__low2float(mn), __high2float(mn));
            float simb = 1.f - __popc(qb[qbase+i] ^ kr)*(1.f/32.f);
            Sout[(size_t)i*1024] = (fw0*simb - fw1*mnf + fw2*(da + db)) * SCALEF;
        }
    }
}

// ---------------- stage 2: row softmax stats (1 warp / row) ----------------
__device__ __forceinline__ float wredmax(float v) {
    #pragma unroll
    for (int o = 16; o; o >>= 1) v = fmaxf(v, __shfl_xor_sync(0xffffffffu, v, o));
    return v;
}
__device__ __forceinline__ float wredsum(float v) {
    #pragma unroll
    for (int o = 16; o; o >>= 1) v += __shfl_xor_sync(0xffffffffu, v, o);
    return v;
}

__global__ __launch_bounds__(256) void stats_kernel()
{
    int gw   = (blockIdx.x * blockDim.x + threadIdx.x) >> 5;  // row 0..8191
    int lane = threadIdx.x & 31;
    const float4* srow = (const float4*)(g_S + ((size_t)gw << 10));
    float4 v[8];
    float mx = -INFINITY;
    #pragma unroll
    for (int j = 0; j < 8; ++j) {
        v[j] = srow[j*32 + lane];
        mx = fmaxf(mx, fmaxf(fmaxf(v[j].x, v[j].y), fmaxf(v[j].z, v[j].w)));
    }
    mx = wredmax(mx);
    float s = 0.f;
    #pragma unroll
    for (int j = 0; j < 8; ++j)
        s += __expf(v[j].x-mx) + __expf(v[j].y-mx) + __expf(v[j].z-mx) + __expf(v[j].w-mx);
    s = wredsum(s);
    if (lane == 0) { g_m[gw] = mx; g_il[gw] = 1.f/s; }
}

// ---------------- host launch ----------------
extern "C" void kernel_launch(void* const* d_in, const int* in_sizes, int n_in,
                              void* d_out, int out_size)
{
    const float* Q        = (const float*)d_in[0];
    const float* K        = (const float*)d_in[1];
    const float* V        = (const float*)d_in[2];
    const float* bq_w     = (const float*)d_in[3];
    const float* bq_b     = (const float*)d_in[4];
    const float* bk_w     = (const float*)d_in[5];
    const float* bk_b     = (const float*)d_in[6];
    const float* b_v      = (const float*)d_in[7];
    const float* tq_w     = (const float*)d_in[8];
    const float* tq_b     = (const float*)d_in[9];
    const float* tk_w     = (const float*)d_in[10];
    const float* tk_b     = (const float*)d_in[11];
    const float* t_v      = (const float*)d_in[12];
    const float* t_temp   = (const float*)d_in[13];
    const float* rq_w     = (const float*)d_in[14];
    const float* rq_b     = (const float*)d_in[15];
    const float* rk_w     = (const float*)d_in[16];
    const float* rk_b     = (const float*)d_in[17];
    const float* r_v      = (const float*)d_in[18];
    const float* pq_w     = (const float*)d_in[19];
    const float* pq_b     = (const float*)d_in[20];
    const float* pk_w     = (const float*)d_in[21];
    const float* pk_b     = (const float*)d_in[22];
    const float* p_v      = (const float*)d_in[23];
    const float* p_fusion = (const float*)d_in[24];
    const float* out_w    = (const float*)d_in[25];
    const float* out_b    = (const float*)d_in[26];
    float* out = (float*)d_out;

    void *pVp, *pcat;
    cudaGetSymbolAddress(&pVp,  g_Vp);
    cudaGetSymbolAddress(&pcat, g_cat);

    // Q/K projections (exact fp32, weights read directly; no pack kernel)
    gemm_qk<<<dim3(3, 32, 2), 256>>>(Q, K,
                                     bq_w, tq_w, rq_w, pq_w,
                                     bk_w, tk_w, rk_w, pk_w,
                                     bq_b, tq_b, rq_b, pq_b,
                                     bk_b, tk_b, rk_b, pk_b);

    // V projection (fp16 tensor cores, BK=32, per head via z)
    gemm_tcv512<<<dim3(2, 16, 4), 512>>>(V, b_v, t_v, r_v, p_v, (float*)pVp);

    pack_bits<<<NTOK*32/256, 256>>>();

    // stage 1: all scores
    scores_kernel<<<dim3(16, 16, 8), 256>>>(t_temp, p_fusion);

    // stage 2: exact softmax stats
    stats_kernel<<<1024, 256>>>();

    // stage 3: exp-weighted PV fp16 tensor-core GEMM (BK=32) -> g_cat
    gemm_pv512<<<dim3(2, 8, 8), 512>>>();

    // output projection (fp16 tensor cores, BK=32)
    gemm_tc512<<<dim3(8, 16), 512>>>((const float*)pcat, out_w, out_b,
                                     out, DIM, DIM);
}

// round 13
// speedup vs baseline: 1.1761x; 1.0082x over previous
#include <cuda_runtime.h>
#include <cuda_fp16.h>
#include <math.h>

// ---------------- problem constants ----------------
#define BATCH 2
#define SEQ   1024
#define DIM   1024
#define HDIM  256
#define MBITS 32
#define NTOK  (BATCH*SEQ)     // 2048
#define PROJ  192             // 6 groups x 32
#define SCALEF 0.17677669529663687f  // 1/sqrt(32)

// ---------------- device scratch (static, no allocs) ----------------
__device__ float    g_qproj[NTOK*PROJ];
__device__ float    g_kproj[NTOK*PROJ];
__device__ unsigned g_qbits[NTOK*2];
__device__ unsigned g_kbits[NTOK*2];
__device__ float    g_Vp[NTOK*4*HDIM];
__device__ unsigned g_cat[NTOK*512];        // half2 k-pairs, 4MB
__device__ float    g_S[8u*1024u*1024u];    // fp32 scores, 32MB
__device__ unsigned g_P[8u*1024u*512u];     // half2 softmax probs, 16MB

// ---------------- fp16 mma helpers ----------------
__device__ __forceinline__ unsigned pack_h2(float lo, float hi) {
    __half2 h = __floats2half2_rn(lo, hi);
    return *(unsigned*)&h;
}
__device__ __forceinline__ void mma_f16(float c[4],
    unsigned a0, unsigned a1, unsigned a2, unsigned a3,
    unsigned b0, unsigned b1)
{
    asm("mma.sync.aligned.m16n8k16.row.col.f32.f16.f16.f32 "
        "{%0,%1,%2,%3},{%4,%5,%6,%7},{%8,%9},{%0,%1,%2,%3};"
        : "+f"(c[0]), "+f"(c[1]), "+f"(c[2]), "+f"(c[3])
        : "r"(a0), "r"(a1), "r"(a2), "r"(a3), "r"(b0), "r"(b1));
}

// ======== 256-thread fp16 GEMM core: 64x128 tile, BK=32 (float A, float W) ==
// A[M,K] fp32 row-major, W[N,K] fp32 row-major (B^T), C fp32 row-major.
__device__ __forceinline__ void tc256h_core(
    const float* __restrict__ A, const float* __restrict__ W,
    const float* __restrict__ bias, float* __restrict__ C,
    int K, int ldc, int bm, int bn)
{
    __shared__ unsigned As[2][16][72];
    __shared__ unsigned Ws[2][16][136];

    const int tid = threadIdx.x;
    const int w = tid >> 5, lane = tid & 31;
    const int wm = w >> 2, wn = w & 3;          // 2x4 warp grid, 32x32 tiles
    const int qr = lane >> 2, qc = lane & 3;

    const int asrow = tid >> 2, aq = tid & 3, askk = aq * 4;
    const int wrow  = tid >> 1, wkk = (tid & 1) * 8;
    const float* Aptr = A + (size_t)(bm + asrow)*K + aq*8;
    const float* Wptr = W + (size_t)(bn + wrow)*K + (tid & 1)*16;

    float acc[2][4][4];
    #pragma unroll
    for (int i = 0; i < 2; ++i)
        #pragma unroll
        for (int j = 0; j < 4; ++j)
            #pragma unroll
            for (int r = 0; r < 4; ++r) acc[i][j][r] = 0.f;

    const int nt = K >> 5;
    float4 a0 = *(const float4*)Aptr;
    float4 a1 = *(const float4*)(Aptr + 4);
    float4 w0 = *(const float4*)Wptr;
    float4 w1 = *(const float4*)(Wptr + 4);
    float4 w2 = *(const float4*)(Wptr + 8);
    float4 w3 = *(const float4*)(Wptr + 12);
    {
        As[0][askk+0][asrow] = pack_h2(a0.x, a0.y);
        As[0][askk+1][asrow] = pack_h2(a0.z, a0.w);
        As[0][askk+2][asrow] = pack_h2(a1.x, a1.y);
        As[0][askk+3][asrow] = pack_h2(a1.z, a1.w);
        Ws[0][wkk+0][wrow] = pack_h2(w0.x, w0.y);
        Ws[0][wkk+1][wrow] = pack_h2(w0.z, w0.w);
        Ws[0][wkk+2][wrow] = pack_h2(w1.x, w1.y);
        Ws[0][wkk+3][wrow] = pack_h2(w1.z, w1.w);
        Ws[0][wkk+4][wrow] = pack_h2(w2.x, w2.y);
        Ws[0][wkk+5][wrow] = pack_h2(w2.z, w2.w);
        Ws[0][wkk+6][wrow] = pack_h2(w3.x, w3.y);
        Ws[0][wkk+7][wrow] = pack_h2(w3.z, w3.w);
    }
    __syncthreads();

    for (int t = 0; t < nt; ++t) {
        const int cur = t & 1;
        if (t + 1 < nt) {
            a0 = *(const float4*)(Aptr + (t+1)*32);
            a1 = *(const float4*)(Aptr + (t+1)*32 + 4);
            w0 = *(const float4*)(Wptr + (t+1)*32);
            w1 = *(const float4*)(Wptr + (t+1)*32 + 4);
            w2 = *(const float4*)(Wptr + (t+1)*32 + 8);
            w3 = *(const float4*)(Wptr + (t+1)*32 + 12);
        }
        #pragma unroll
        for (int ks = 0; ks < 2; ++ks) {
            const int kb = ks*8;
            unsigned af[2][4], bf[4][2];
            #pragma unroll
            for (int i = 0; i < 2; ++i) {
                int m0 = wm*32 + i*16 + qr;
                af[i][0] = As[cur][kb+qc  ][m0];
                af[i][1] = As[cur][kb+qc  ][m0+8];
                af[i][2] = As[cur][kb+qc+4][m0];
                af[i][3] = As[cur][kb+qc+4][m0+8];
            }
            #pragma unroll
            for (int j = 0; j < 4; ++j) {
                int n0 = wn*32 + j*8 + qr;
                bf[j][0] = Ws[cur][kb+qc  ][n0];
                bf[j][1] = Ws[cur][kb+qc+4][n0];
            }
            #pragma unroll
            for (int i = 0; i < 2; ++i)
                #pragma unroll
                for (int j = 0; j < 4; ++j)
                    mma_f16(acc[i][j], af[i][0], af[i][1], af[i][2], af[i][3],
                            bf[j][0], bf[j][1]);
        }
        if (t + 1 < nt) {
            const int nxt = cur ^ 1;
            As[nxt][askk+0][asrow] = pack_h2(a0.x, a0.y);
            As[nxt][askk+1][asrow] = pack_h2(a0.z, a0.w);
            As[nxt][askk+2][asrow] = pack_h2(a1.x, a1.y);
            As[nxt][askk+3][asrow] = pack_h2(a1.z, a1.w);
            Ws[nxt][wkk+0][wrow] = pack_h2(w0.x, w0.y);
            Ws[nxt][wkk+1][wrow] = pack_h2(w0.z, w0.w);
            Ws[nxt][wkk+2][wrow] = pack_h2(w1.x, w1.y);
            Ws[nxt][wkk+3][wrow] = pack_h2(w1.z, w1.w);
            Ws[nxt][wkk+4][wrow] = pack_h2(w2.x, w2.y);
            Ws[nxt][wkk+5][wrow] = pack_h2(w2.z, w2.w);
            Ws[nxt][wkk+6][wrow] = pack_h2(w3.x, w3.y);
            Ws[nxt][wkk+7][wrow] = pack_h2(w3.z, w3.w);
        }
        __syncthreads();
    }

    #pragma unroll
    for (int i = 0; i < 2; ++i) {
        int r0 = bm + wm*32 + i*16 + qr;
        #pragma unroll
        for (int j = 0; j < 4; ++j) {
            int c0 = bn + wn*32 + j*8 + 2*qc;
            float bx = 0.f, by = 0.f;
            if (bias) { bx = bias[c0]; by = bias[c0+1]; }
            float2 o0, o1;
            o0.x = acc[i][j][0] + bx; o0.y = acc[i][j][1] + by;
            o1.x = acc[i][j][2] + bx; o1.y = acc[i][j][3] + by;
            *(float2*)&C[(size_t)r0*ldc + c0]     = o0;
            *(float2*)&C[(size_t)(r0+8)*ldc + c0] = o1;
        }
    }
}

// V projection per head: grid (2, 32, 4)
__global__ __launch_bounds__(256) void gemm_tcv256(
    const float* __restrict__ V,
    const float* __restrict__ w0, const float* __restrict__ w1,
    const float* __restrict__ w2, const float* __restrict__ w3,
    float* __restrict__ C)
{
    const float* W = (blockIdx.z == 0) ? w0 : (blockIdx.z == 1) ? w1
                   : (blockIdx.z == 2) ? w2 : w3;
    tc256h_core(V, W, nullptr, C + blockIdx.z*HDIM,
                DIM, 4*HDIM, blockIdx.y*64, blockIdx.x*128);
}

// ======== out-proj: A = g_cat (half2 pairs), W = out_w fp32; grid (8,32) ====
__global__ __launch_bounds__(256) void gemm_out256(
    const float* __restrict__ Wout, const float* __restrict__ bias,
    float* __restrict__ C)
{
    __shared__ unsigned As[2][16][72];
    __shared__ unsigned Ws[2][16][136];

    const int bm = blockIdx.y * 64, bn = blockIdx.x * 128;
    const int tid = threadIdx.x;
    const int w = tid >> 5, lane = tid & 31;
    const int wm = w >> 2, wn = w & 3;
    const int qr = lane >> 2, qc = lane & 3;

    const int asrow = tid >> 2, aq = tid & 3, askk = aq * 4;
    const int wrow  = tid >> 1, wkk = (tid & 1) * 8;
    const unsigned* Aptr = g_cat + (size_t)(bm + asrow)*512 + aq*4;
    const float* Wptr = Wout + (size_t)(bn + wrow)*DIM + (tid & 1)*16;

    float acc[2][4][4];
    #pragma unroll
    for (int i = 0; i < 2; ++i)
        #pragma unroll
        for (int j = 0; j < 4; ++j)
            #pragma unroll
            for (int r = 0; r < 4; ++r) acc[i][j][r] = 0.f;

    const int nt = DIM >> 5;  // 32
    uint4 au = *(const uint4*)Aptr;
    float4 w0 = *(const float4*)Wptr;
    float4 w1 = *(const float4*)(Wptr + 4);
    float4 w2 = *(const float4*)(Wptr + 8);
    float4 w3 = *(const float4*)(Wptr + 12);
    {
        As[0][askk+0][asrow] = au.x;
        As[0][askk+1][asrow] = au.y;
        As[0][askk+2][asrow] = au.z;
        As[0][askk+3][asrow] = au.w;
        Ws[0][wkk+0][wrow] = pack_h2(w0.x, w0.y);
        Ws[0][wkk+1][wrow] = pack_h2(w0.z, w0.w);
        Ws[0][wkk+2][wrow] = pack_h2(w1.x, w1.y);
        Ws[0][wkk+3][wrow] = pack_h2(w1.z, w1.w);
        Ws[0][wkk+4][wrow] = pack_h2(w2.x, w2.y);
        Ws[0][wkk+5][wrow] = pack_h2(w2.z, w2.w);
        Ws[0][wkk+6][wrow] = pack_h2(w3.x, w3.y);
        Ws[0][wkk+7][wrow] = pack_h2(w3.z, w3.w);
    }
    __syncthreads();

    for (int t = 0; t < nt; ++t) {
        const int cur = t & 1;
        if (t + 1 < nt) {
            au = *(const uint4*)(Aptr + (t+1)*16);
            w0 = *(const float4*)(Wptr + (t+1)*32);
            w1 = *(const float4*)(Wptr + (t+1)*32 + 4);
            w2 = *(const float4*)(Wptr + (t+1)*32 + 8);
            w3 = *(const float4*)(Wptr + (t+1)*32 + 12);
        }
        #pragma unroll
        for (int ks = 0; ks < 2; ++ks) {
            const int kb = ks*8;
            unsigned af[2][4], bf[4][2];
            #pragma unroll
            for (int i = 0; i < 2; ++i) {
                int m0 = wm*32 + i*16 + qr;
                af[i][0] = As[cur][kb+qc  ][m0];
                af[i][1] = As[cur][kb+qc  ][m0+8];
                af[i][2] = As[cur][kb+qc+4][m0];
                af[i][3] = As[cur][kb+qc+4][m0+8];
            }
            #pragma unroll
            for (int j = 0; j < 4; ++j) {
                int n0 = wn*32 + j*8 + qr;
                bf[j][0] = Ws[cur][kb+qc  ][n0];
                bf[j][1] = Ws[cur][kb+qc+4][n0];
            }
            #pragma unroll
            for (int i = 0; i < 2; ++i)
                #pragma unroll
                for (int j = 0; j < 4; ++j)
                    mma_f16(acc[i][j], af[i][0], af[i][1], af[i][2], af[i][3],
                            bf[j][0], bf[j][1]);
        }
        if (t + 1 < nt) {
            const int nxt = cur ^ 1;
            As[nxt][askk+0][asrow] = au.x;
            As[nxt][askk+1][asrow] = au.y;
            As[nxt][askk+2][asrow] = au.z;
            As[nxt][askk+3][asrow] = au.w;
            Ws[nxt][wkk+0][wrow] = pack_h2(w0.x, w0.y);
            Ws[nxt][wkk+1][wrow] = pack_h2(w0.z, w0.w);
            Ws[nxt][wkk+2][wrow] = pack_h2(w1.x, w1.y);
            Ws[nxt][wkk+3][wrow] = pack_h2(w1.z, w1.w);
            Ws[nxt][wkk+4][wrow] = pack_h2(w2.x, w2.y);
            Ws[nxt][wkk+5][wrow] = pack_h2(w2.z, w2.w);
            Ws[nxt][wkk+6][wrow] = pack_h2(w3.x, w3.y);
            Ws[nxt][wkk+7][wrow] = pack_h2(w3.z, w3.w);
        }
        __syncthreads();
    }

    #pragma unroll
    for (int i = 0; i < 2; ++i) {
        int r0 = bm + wm*32 + i*16 + qr;
        #pragma unroll
        for (int j = 0; j < 4; ++j) {
            int c0 = bn + wn*32 + j*8 + 2*qc;
            float bx = bias[c0], by = bias[c0+1];
            float2 o0, o1;
            o0.x = acc[i][j][0] + bx; o0.y = acc[i][j][1] + by;
            o1.x = acc[i][j][2] + bx; o1.y = acc[i][j][3] + by;
            *(float2*)&C[(size_t)r0*DIM + c0]     = o0;
            *(float2*)&C[(size_t)(r0+8)*DIM + c0] = o1;
        }
    }
}

// ======== PV: A = g_P (half2), W = Vp fp32 k-major; grid (2,16,8) ==========
__global__ __launch_bounds__(256) void gemm_pv256()
{
    __shared__ unsigned As[2][16][72];
    __shared__ unsigned Ws[2][16][136];

    const int bh = blockIdx.z, b = bh >> 2, head = bh & 3;
    const int bm = blockIdx.y * 64, bn = blockIdx.x * 128;
    const int tid = threadIdx.x;
    const int w = tid >> 5, lane = tid & 31;
    const int wm = w >> 2, wn = w & 3;
    const int qr = lane >> 2, qc = lane & 3;

    const int asrow = tid >> 2, aq = tid & 3, askk = aq * 4;
    const unsigned* Aptr = g_P + ((size_t)bh << 19) + (size_t)(bm + asrow)*512 + aq*4;
    const int kq = tid >> 5, n4 = tid & 31;   // W staging: slots kq, kq+8
    const float* Wptr = g_Vp + (size_t)(b*SEQ + 2*kq)*1024 + head*HDIM + bn + n4*4;

    float acc[2][4][4];
    #pragma unroll
    for (int i = 0; i < 2; ++i)
        #pragma unroll
        for (int j = 0; j < 4; ++j)
            #pragma unroll
            for (int r = 0; r < 4; ++r) acc[i][j][r] = 0.f;

    const int nt = 32;  // K=1024, BK=32
    uint4 au = *(const uint4*)Aptr;
    float4 w0 = *(const float4*)Wptr;
    float4 w1 = *(const float4*)(Wptr + 1024);
    float4 w2 = *(const float4*)(Wptr + 16*1024);
    float4 w3 = *(const float4*)(Wptr + 17*1024);
    {
        As[0][askk+0][asrow] = au.x;
        As[0][askk+1][asrow] = au.y;
        As[0][askk+2][asrow] = au.z;
        As[0][askk+3][asrow] = au.w;
        #pragma unroll
        for (int j = 0; j < 4; ++j) {
            Ws[0][kq  ][n4*4+j] = pack_h2((&w0.x)[j], (&w1.x)[j]);
            Ws[0][kq+8][n4*4+j] = pack_h2((&w2.x)[j], (&w3.x)[j]);
        }
    }
    __syncthreads();

    for (int t = 0; t < nt; ++t) {
        const int cur = t & 1;
        if (t + 1 < nt) {
            au = *(const uint4*)(Aptr + (t+1)*16);
            const float* p = Wptr + (size_t)(t+1)*32*1024;
            w0 = *(const float4*)p;
            w1 = *(const float4*)(p + 1024);
            w2 = *(const float4*)(p + 16*1024);
            w3 = *(const float4*)(p + 17*1024);
        }
        #pragma unroll
        for (int ks = 0; ks < 2; ++ks) {
            const int kb = ks*8;
            unsigned af[2][4], bf[4][2];
            #pragma unroll
            for (int i = 0; i < 2; ++i) {
                int m0 = wm*32 + i*16 + qr;
                af[i][0] = As[cur][kb+qc  ][m0];
                af[i][1] = As[cur][kb+qc  ][m0+8];
                af[i][2] = As[cur][kb+qc+4][m0];
                af[i][3] = As[cur][kb+qc+4][m0+8];
            }
            #pragma unroll
            for (int j = 0; j < 4; ++j) {
                int n0 = wn*32 + j*8 + qr;
                bf[j][0] = Ws[cur][kb+qc  ][n0];
                bf[j][1] = Ws[cur][kb+qc+4][n0];
            }
            #pragma unroll
            for (int i = 0; i < 2; ++i)
                #pragma unroll
                for (int j = 0; j < 4; ++j)
                    mma_f16(acc[i][j], af[i][0], af[i][1], af[i][2], af[i][3],
                            bf[j][0], bf[j][1]);
        }
        if (t + 1 < nt) {
            const int nxt = cur ^ 1;
            As[nxt][askk+0][asrow] = au.x;
            As[nxt][askk+1][asrow] = au.y;
            As[nxt][askk+2][asrow] = au.z;
            As[nxt][askk+3][asrow] = au.w;
            #pragma unroll
            for (int j = 0; j < 4; ++j) {
                Ws[nxt][kq  ][n4*4+j] = pack_h2((&w0.x)[j], (&w1.x)[j]);
                Ws[nxt][kq+8][n4*4+j] = pack_h2((&w2.x)[j], (&w3.x)[j]);
            }
        }
        __syncthreads();
    }

    // epilogue: write half2 pairs into g_cat (cols within head slice)
    unsigned* Cb = g_cat + (size_t)(b*SEQ)*512 + head*(HDIM/2);
    #pragma unroll
    for (int i = 0; i < 2; ++i) {
        int r0 = bm + wm*32 + i*16 + qr;
        #pragma unroll
        for (int j = 0; j < 4; ++j) {
            int c0 = bn + wn*32 + j*8 + 2*qc;
            Cb[(size_t)r0*512 + (c0>>1)]     = pack_h2(acc[i][j][0], acc[i][j][1]);
            Cb[(size_t)(r0+8)*512 + (c0>>1)] = pack_h2(acc[i][j][2], acc[i][j][3]);
        }
    }
}

// ---------------- fp32 QK projection GEMM: 64x64 tiles, direct weights ----
__global__ __launch_bounds__(256) void gemm_qk(
    const float* __restrict__ Qin, const float* __restrict__ Kin,
    const float* __restrict__ bq_w, const float* __restrict__ tq_w,
    const float* __restrict__ rq_w, const float* __restrict__ pq_w,
    const float* __restrict__ bk_w, const float* __restrict__ tk_w,
    const float* __restrict__ rk_w, const float* __restrict__ pk_w,
    const float* __restrict__ bq_b, const float* __restrict__ tq_b,
    const float* __restrict__ rq_b, const float* __restrict__ pq_b,
    const float* __restrict__ bk_b, const float* __restrict__ tk_b,
    const float* __restrict__ rk_b, const float* __restrict__ pk_b)
{
    __shared__ __align__(16) float As[2][8][68];
    __shared__ __align__(16) float Ws[2][8][68];

    const int z = blockIdx.z;
    const float* A = z ? Kin : Qin;
    float*       C = z ? g_kproj : g_qproj;
    const float* wsrc[6];
    const float* bsrc[6];
    if (z) {
        wsrc[0]=bk_w; wsrc[1]=tk_w; wsrc[2]=rk_w;
        wsrc[3]=pk_w; wsrc[4]=pk_w+(size_t)32*DIM; wsrc[5]=pk_w+(size_t)64*DIM;
        bsrc[0]=bk_b; bsrc[1]=tk_b; bsrc[2]=rk_b;
        bsrc[3]=pk_b; bsrc[4]=pk_b+32; bsrc[5]=pk_b+64;
    } else {
        wsrc[0]=bq_w; wsrc[1]=tq_w; wsrc[2]=rq_w;
        wsrc[3]=pq_w; wsrc[4]=pq_w+(size_t)32*DIM; wsrc[5]=pq_w+(size_t)64*DIM;
        bsrc[0]=bq_b; bsrc[1]=tq_b; bsrc[2]=rq_b;
        bsrc[3]=pq_b; bsrc[4]=pq_b+32; bsrc[5]=pq_b+64;
    }

    const int bm = blockIdx.y * 64, bn = blockIdx.x * 64;
    const int tid = threadIdx.x;
    const int tx = tid & 15, ty = tid >> 4;

    const bool isA = tid < 128;
    const int st = isA ? tid : tid - 128;
    const int srow = st >> 1, sc4 = (st & 1) * 4;
    const float* Sptr;
    if (isA) Sptr = A + (size_t)(bm + srow)*DIM + sc4;
    else {
        int wr = bn + srow;
        Sptr = wsrc[wr >> 5] + (size_t)(wr & 31)*DIM + sc4;
    }

    float acc[4][4];
    #pragma unroll
    for (int i = 0; i < 4; ++i)
        #pragma unroll
        for (int j = 0; j < 4; ++j) acc[i][j] = 0.f;

    const int nt = DIM >> 3;  // 128
    float4 sreg = *(const float4*)Sptr;
    #pragma unroll
    for (int j = 0; j < 4; ++j) {
        if (isA) As[0][sc4+j][srow] = (&sreg.x)[j];
        else     Ws[0][sc4+j][srow] = (&sreg.x)[j];
    }
    __syncthreads();

    for (int t = 0; t < nt; ++t) {
        const int cur = t & 1;
        if (t + 1 < nt) sreg = *(const float4*)(Sptr + (t+1)*8);
        #pragma unroll
        for (int kk = 0; kk < 8; ++kk) {
            float4 a4 = *(const float4*)&As[cur][kk][ty*4];
            float4 b4 = *(const float4*)&Ws[cur][kk][tx*4];
            const float* a = &a4.x;
            const float* b = &b4.x;
            #pragma unroll
            for (int i = 0; i < 4; ++i)
                #pragma unroll
                for (int j = 0; j < 4; ++j)
                    acc[i][j] += a[i]*b[j];
        }
        if (t + 1 < nt) {
            const int nxt = cur ^ 1;
            #pragma unroll
            for (int j = 0; j < 4; ++j) {
                if (isA) As[nxt][sc4+j][srow] = (&sreg.x)[j];
                else     Ws[nxt][sc4+j][srow] = (&sreg.x)[j];
            }
        }
        __syncthreads();
    }

    const int col = bn + tx*4;
    const float* bb = bsrc[col >> 5] + (col & 31);
    #pragma unroll
    for (int i = 0; i < 4; ++i) {
        int row = bm + ty*4 + i;
        float4 o;
        o.x = acc[i][0] + bb[0];
        o.y = acc[i][1] + bb[1];
        o.z = acc[i][2] + bb[2];
        o.w = acc[i][3] + bb[3];
        *(float4*)&C[(size_t)row*PROJ + col] = o;
    }
}

// ---------------- bit packing for boolean heads ----------------
__global__ void pack_bits()
{
    int gw = (blockIdx.x * blockDim.x + threadIdx.x) >> 5;
    int lane = threadIdx.x & 31;
    if (gw >= NTOK) return;
    unsigned q0 = __ballot_sync(0xffffffffu, g_qproj[(size_t)gw*PROJ + lane]       > 0.f);
    unsigned q1 = __ballot_sync(0xffffffffu, g_qproj[(size_t)gw*PROJ + 96 + lane]  > 0.f);
    unsigned k0 = __ballot_sync(0xffffffffu, g_kproj[(size_t)gw*PROJ + lane]       > 0.f);
    unsigned k1 = __ballot_sync(0xffffffffu, g_kproj[(size_t)gw*PROJ + 96 + lane]  > 0.f);
    if (lane == 0) {
        g_qbits[gw*2]   = q0; g_qbits[gw*2+1] = q1;
        g_kbits[gw*2]   = k0; g_kbits[gw*2+1] = k1;
    }
}

// ---------------- stage 1: scores (64q x 64k tiles) ----
#define RE_STRIDE 34
#define TR_STRIDE 17

__global__ __launch_bounds__(256) void scores_kernel(
    const float* __restrict__ t_temp, const float* __restrict__ p_fusion)
{
    __shared__ float    qer[64*RE_STRIDE];
    __shared__ float    ker[64*RE_STRIDE];
    __shared__ __half2  qet[64*TR_STRIDE];
    __shared__ __half2  ket[64*TR_STRIDE];
    __shared__ unsigned qb[64], kb[64];

    const int k0  = blockIdx.x * 64;
    const int n0  = blockIdx.y * 64;
    const int bh  = blockIdx.z;
    const int b   = bh >> 2, head = bh & 3;
    const int tid = threadIdx.x;

    float inv_sp = 1.f;
    if (head == 1) inv_sp = 1.f / log1pf(expf(t_temp[0]));
    float fw0 = 0.f, fw1 = 0.f, fw2 = 0.f;
    if (head == 3) {
        float p0 = p_fusion[0], p1 = p_fusion[1], p2 = p_fusion[2];
        float mx = fmaxf(p0, fmaxf(p1, p2));
        float e0 = expf(p0-mx), e1 = expf(p1-mx), e2 = expf(p2-mx);
        float inv = 1.f/(e0+e1+e2);
        fw0 = e0*inv; fw1 = e1*inv; fw2 = e2*inv;
    }

    if (head == 0) {
        if (tid < 64)       qb[tid]    = g_qbits[(b*SEQ + n0 + tid)*2];
        else if (tid < 128) kb[tid-64] = g_kbits[(b*SEQ + k0 + tid-64)*2];
    } else if (head == 1) {
        for (int j = tid; j < 1024; j += 256) {
            int t = j >> 4, m = j & 15;
            const float* bq_ = &g_qproj[(size_t)(b*SEQ + n0 + t)*PROJ];
            const float* bk_ = &g_kproj[(size_t)(b*SEQ + k0 + t)*PROJ];
            qet[t*TR_STRIDE+m] = __floats2half2_rn(bq_[32+2*m], bq_[33+2*m]);
            ket[t*TR_STRIDE+m] = __floats2half2_rn(bk_[32+2*m], bk_[33+2*m]);
        }
    } else if (head == 2) {
        for (int j = tid; j < 2048; j += 256) {
            int t = j >> 5, m = j & 31;
            qer[t*RE_STRIDE+m] = g_qproj[(size_t)(b*SEQ + n0 + t)*PROJ + 64 + m];
            ker[t*RE_STRIDE+m] = g_kproj[(size_t)(b*SEQ + k0 + t)*PROJ + 64 + m];
        }
    } else {
        if (tid < 64)       qb[tid]    = g_qbits[(b*SEQ + n0 + tid)*2 + 1];
        else if (tid < 128) kb[tid-64] = g_kbits[(b*SEQ + k0 + tid-64)*2 + 1];
        for (int j = tid; j < 1024; j += 256) {
            int t = j >> 4, m = j & 15;
            const float* bq_ = &g_qproj[(size_t)(b*SEQ + n0 + t)*PROJ];
            const float* bk_ = &g_kproj[(size_t)(b*SEQ + k0 + t)*PROJ];
            qet[t*TR_STRIDE+m] = __floats2half2_rn(bq_[128+2*m], bq_[129+2*m]);
            ket[t*TR_STRIDE+m] = __floats2half2_rn(bk_[128+2*m], bk_[129+2*m]);
        }
        for (int j = tid; j < 2048; j += 256) {
            int t = j >> 5, m = j & 31;
            qer[t*RE_STRIDE+m] = g_qproj[(size_t)(b*SEQ + n0 + t)*PROJ + 160 + m];
            ker[t*RE_STRIDE+m] = g_kproj[(size_t)(b*SEQ + k0 + t)*PROJ + 160 + m];
        }
    }
    __syncthreads();

    const int kk    = tid & 63;
    const int qbase = (tid >> 6) * 16;
    float* Sout = g_S + ((size_t)bh << 20) + (size_t)(n0 + qbase)*1024 + k0 + kk;

    if (head == 0) {
        unsigned kr = kb[kk];
        #pragma unroll
        for (int i = 0; i < 16; ++i) {
            int p = __popc(qb[qbase+i] ^ kr);
            Sout[(size_t)i*1024] = (1.f - p*(1.f/32.f)) * SCALEF;
        }
    } else if (head == 1) {
        __half2 kr[16];
        const __half2* krow = &ket[kk*TR_STRIDE];
        #pragma unroll
        for (int m = 0; m < 16; ++m) kr[m] = krow[m];
        #pragma unroll 4
        for (int i = 0; i < 16; ++i) {
            const __half2* qe = &qet[(qbase+i)*TR_STRIDE];
            __half2 mA = __hadd2(qe[0], kr[0]);
            __half2 mB = __hadd2(qe[1], kr[1]);
            __half2 mC = __hadd2(qe[2], kr[2]);
            __half2 mD = __hadd2(qe[3], kr[3]);
            #pragma unroll
            for (int m = 4; m < 16; m += 4) {
                mA = __hmin2(mA, __hadd2(qe[m],   kr[m]));
                mB = __hmin2(mB, __hadd2(qe[m+1], kr[m+1]));
                mC = __hmin2(mC, __hadd2(qe[m+2], kr[m+2]));
                mD = __hmin2(mD, __hadd2(qe[m+3], kr[m+3]));
            }
            __half2 mn = __hmin2(__hmin2(mA, mB), __hmin2(mC, mD));
            float mnf = fminf(__low2float(mn), __high2float(mn));
            Sout[(size_t)i*1024] = -mnf * inv_sp;
        }
    } else if (head == 2) {
        float krr[32];
        const float* krow = &ker[kk*RE_STRIDE];
        #pragma unroll
        for (int m = 0; m < 32; ++m) krr[m] = krow[m];
        #pragma unroll 4
        for (int i = 0; i < 16; ++i) {
            const float* qe = &qer[(qbase+i)*RE_STRIDE];
            float da = 0.f, db = 0.f, dc = 0.f, dd = 0.f;
            #pragma unroll
            for (int m = 0; m < 32; m += 4) {
                da = fmaf(qe[m],   krr[m],   da);
                db = fmaf(qe[m+1], krr[m+1], db);
                dc = fmaf(qe[m+2], krr[m+2], dc);
                dd = fmaf(qe[m+3], krr[m+3], dd);
            }
            Sout[(size_t)i*1024] = ((da + db) + (dc + dd)) * SCALEF;
        }
    } else {
        __half2 krt[16];
        float krr[32];
        const __half2* ktrow = &ket[kk*TR_STRIDE];
        const float* krrow = &ker[kk*RE_STRIDE];
        #pragma unroll
        for (int m = 0; m < 16; ++m) krt[m] = ktrow[m];
        #pragma unroll
        for (int m = 0; m < 32; ++m) krr[m] = krrow[m];
        unsigned kr = kb[kk];
        #pragma unroll 2
        for (int i = 0; i < 16; ++i) {
            const __half2* qe = &qet[(qbase+i)*TR_STRIDE];
            const float* qf  = &qer[(qbase+i)*RE_STRIDE];
            __half2 mA = __hadd2(qe[0], krt[0]);
            __half2 mB = __hadd2(qe[1], krt[1]);
            __half2 mC = __hadd2(qe[2], krt[2]);
            __half2 mD = __hadd2(qe[3], krt[3]);
            float da = 0.f, db = 0.f, dc = 0.f, dd = 0.f;
            #pragma unroll
            for (int m = 4; m < 16; m += 4) {
                mA = __hmin2(mA, __hadd2(qe[m],   krt[m]));
                mB = __hmin2(mB, __hadd2(qe[m+1], krt[m+1]));
                mC = __hmin2(mC, __hadd2(qe[m+2], krt[m+2]));
                mD = __hmin2(mD, __hadd2(qe[m+3], krt[m+3]));
            }
            #pragma unroll
            for (int m = 0; m < 32; m += 4) {
                da = fmaf(qf[m],   krr[m],   da);
                db = fmaf(qf[m+1], krr[m+1], db);
                dc = fmaf(qf[m+2], krr[m+2], dc);
                dd = fmaf(qf[m+3], krr[m+3], dd);
            }
            __half2 mn = __hmin2(__hmin2(mA, mB), __hmin2(mC, mD));
            float mnf = fminf(__low2float(mn), __high2float(mn));
            float simb = 1.f - __popc(qb[qbase+i] ^ kr)*(1.f/32.f);
            Sout[(size_t)i*1024] = (fw0*simb - fw1*mnf + fw2*((da+db)+(dc+dd))) * SCALEF;
        }
    }
}

// ---------------- stage 2: softmax stats + write P as half2 ---------------
__device__ __forceinline__ float wredmax(float v) {
    #pragma unroll
    for (int o = 16; o; o >>= 1) v = fmaxf(v, __shfl_xor_sync(0xffffffffu, v, o));
    return v;
}
__device__ __forceinline__ float wredsum(float v) {
    #pragma unroll
    for (int o = 16; o; o >>= 1) v += __shfl_xor_sync(0xffffffffu, v, o);
    return v;
}

__global__ __launch_bounds__(256) void stats_kernel()
{
    int gw   = (blockIdx.x * blockDim.x + threadIdx.x) >> 5;  // row 0..8191
    int lane = threadIdx.x & 31;
    const float4* srow = (const float4*)(g_S + ((size_t)gw << 10));
    float4 v[8];
    float mx = -INFINITY;
    #pragma unroll
    for (int j = 0; j < 8; ++j) {
        v[j] = srow[j*32 + lane];
        mx = fmaxf(mx, fmaxf(fmaxf(v[j].x, v[j].y), fmaxf(v[j].z, v[j].w)));
    }
    mx = wredmax(mx);
    float s = 0.f;
    #pragma unroll
    for (int j = 0; j < 8; ++j) {
        v[j].x = __expf(v[j].x - mx);
        v[j].y = __expf(v[j].y - mx);
        v[j].z = __expf(v[j].z - mx);
        v[j].w = __expf(v[j].w - mx);
        s += (v[j].x + v[j].y) + (v[j].z + v[j].w);
    }
    s = wredsum(s);
    float il = 1.f / s;
    unsigned* prow = g_P + ((size_t)gw << 9);
    #pragma unroll
    for (int j = 0; j < 8; ++j) {
        uint2 o;
        o.x = pack_h2(v[j].x * il, v[j].y * il);
        o.y = pack_h2(v[j].z * il, v[j].w * il);
        *(uint2*)&prow[(j*32 + lane)*2] = o;
    }
}

// ---------------- host launch ----------------
extern "C" void kernel_launch(void* const* d_in, const int* in_sizes, int n_in,
                              void* d_out, int out_size)
{
    const float* Q        = (const float*)d_in[0];
    const float* K        = (const float*)d_in[1];
    const float* V        = (const float*)d_in[2];
    const float* bq_w     = (const float*)d_in[3];
    const float* bq_b     = (const float*)d_in[4];
    const float* bk_w     = (const float*)d_in[5];
    const float* bk_b     = (const float*)d_in[6];
    const float* b_v      = (const float*)d_in[7];
    const float* tq_w     = (const float*)d_in[8];
    const float* tq_b     = (const float*)d_in[9];
    const float* tk_w     = (const float*)d_in[10];
    const float* tk_b     = (const float*)d_in[11];
    const float* t_v      = (const float*)d_in[12];
    const float* t_temp   = (const float*)d_in[13];
    const float* rq_w     = (const float*)d_in[14];
    const float* rq_b     = (const float*)d_in[15];
    const float* rk_w     = (const float*)d_in[16];
    const float* rk_b     = (const float*)d_in[17];
    const float* r_v      = (const float*)d_in[18];
    const float* pq_w     = (const float*)d_in[19];
    const float* pq_b     = (const float*)d_in[20];
    const float* pk_w     = (const float*)d_in[21];
    const float* pk_b     = (const float*)d_in[22];
    const float* p_v      = (const float*)d_in[23];
    const float* p_fusion = (const float*)d_in[24];
    const float* out_w    = (const float*)d_in[25];
    const float* out_b    = (const float*)d_in[26];
    float* out = (float*)d_out;

    void *pVp;
    cudaGetSymbolAddress(&pVp, g_Vp);

    // Q/K projections (exact fp32, weights read directly)
    gemm_qk<<<dim3(3, 32, 2), 256>>>(Q, K,
                                     bq_w, tq_w, rq_w, pq_w,
                                     bk_w, tk_w, rk_w, pk_w,
                                     bq_b, tq_b, rq_b, pq_b,
                                     bk_b, tk_b, rk_b, pk_b);

    // V projection: fp16 mma, 64x128 tiles, 256 blocks
    gemm_tcv256<<<dim3(2, 32, 4), 256>>>(V, b_v, t_v, r_v, p_v, (float*)pVp);

    pack_bits<<<NTOK*32/256, 256>>>();

    // stage 1: all scores
    scores_kernel<<<dim3(16, 16, 8), 256>>>(t_temp, p_fusion);

    // stage 2: softmax stats + P (half2)
    stats_kernel<<<1024, 256>>>();

    // stage 3: PV fp16 GEMM (P from g_P) -> g_cat (half2)
    gemm_pv256<<<dim3(2, 16, 8), 256>>>();

    // output projection (A = g_cat half2)
    gemm_out256<<<dim3(8, 32), 256>>>(out_w, out_b, out);
}